// round 10
// baseline (speedup 1.0000x reference)
#include <cuda_runtime.h>
#include <cuda_bf16.h>

#define BATCH 4
#define S 1024
#define D 1024
#define H 16
#define DK 64

// ---------------------------------------------------------------------------
// scratch (allocation-free: __device__ globals), split bf16: v ~= hi + lo
// ---------------------------------------------------------------------------
__device__ __nv_bfloat16 g_q_hi[BATCH * S * D];
__device__ __nv_bfloat16 g_q_lo[BATCH * S * D];
__device__ __nv_bfloat16 g_k_hi[BATCH * S * D];
__device__ __nv_bfloat16 g_k_lo[BATCH * S * D];
__device__ float g_asco[BATCH * H * S];
__device__ unsigned char g_mask8[BATCH * S * S];   // packed mask bytes

// ---------------------------------------------------------------------------
// helpers
// ---------------------------------------------------------------------------
__device__ __forceinline__ unsigned sm_u32(const void* p) {
    return (unsigned)__cvta_generic_to_shared(p);
}

__device__ __forceinline__ void ldsm4(unsigned r[4], unsigned addr) {
    asm volatile("ldmatrix.sync.aligned.m8n8.x4.shared.b16 {%0,%1,%2,%3}, [%4];"
                 : "=r"(r[0]), "=r"(r[1]), "=r"(r[2]), "=r"(r[3])
                 : "r"(addr));
}

__device__ __forceinline__ void mma16816(float* c, const unsigned* a, const unsigned* b) {
    asm volatile(
        "mma.sync.aligned.m16n8k16.row.col.f32.bf16.bf16.f32 "
        "{%0,%1,%2,%3}, {%4,%5,%6,%7}, {%8,%9}, {%0,%1,%2,%3};"
        : "+f"(c[0]), "+f"(c[1]), "+f"(c[2]), "+f"(c[3])
        : "r"(a[0]), "r"(a[1]), "r"(a[2]), "r"(a[3]), "r"(b[0]), "r"(b[1]));
}

__device__ __forceinline__ void split_pack(float x, float y, unsigned& hi, unsigned& lo) {
    __nv_bfloat162 h, l;
    h.x = __float2bfloat16(x);
    h.y = __float2bfloat16(y);
    l.x = __float2bfloat16(x - __bfloat162float(h.x));
    l.y = __float2bfloat16(y - __bfloat162float(h.y));
    hi = *reinterpret_cast<unsigned*>(&h);
    lo = *reinterpret_cast<unsigned*>(&l);
}

__device__ __forceinline__ void cpa16(unsigned dst, const void* src) {
    asm volatile("cp.async.cg.shared.global [%0], [%1], 16;" :: "r"(dst), "l"(src));
}
#define CP_COMMIT() asm volatile("cp.async.commit_group;")
#define CP_WAIT(N)  asm volatile("cp.async.wait_group %0;" :: "n"(N))

// ---------------------------------------------------------------------------
// Kernel 0: pack mask int32 {0,1} -> uint8 (exact).
// ---------------------------------------------------------------------------
__global__ __launch_bounds__(256) void mask8_kernel(
    const int* __restrict__ m, unsigned char* __restrict__ o, int n4)
{
    int i = blockIdx.x * 256 + threadIdx.x;
    if (i < n4) {
        int4 v = ((const int4*)m)[i];
        uchar4 u;
        u.x = (unsigned char)v.x; u.y = (unsigned char)v.y;
        u.z = (unsigned char)v.z; u.w = (unsigned char)v.w;
        ((uchar4*)o)[i] = u;
    }
}

// ---------------------------------------------------------------------------
// Kernel 1 (round-3 proven, 183us): C = X @ W^T + bias, z in {Q, K}.
// 128x128 CTA tile, BK=32, double-buffered smem, inline fp32->hi/lo convert,
// 3-term split-bf16 mma, 8 warps, warp tile 32x64.
// ---------------------------------------------------------------------------
#define PJ_AHI 0
#define PJ_ALO 10240
#define PJ_BHI 20480
#define PJ_BLO 30720
#define PJ_BUF 40960

__global__ void __launch_bounds__(256, 1) proj_kernel(
    const float* __restrict__ Xq, const float* __restrict__ Wq, const float* __restrict__ bq,
    const float* __restrict__ Xk, const float* __restrict__ Wk, const float* __restrict__ bk)
{
    extern __shared__ char smem_raw[];
    const bool is_k = blockIdx.z != 0;
    const float* __restrict__ X = is_k ? Xk : Xq;
    const float* __restrict__ W = is_k ? Wk : Wq;
    const float* __restrict__ bias = is_k ? bk : bq;
    __nv_bfloat16* __restrict__ Chi = is_k ? g_k_hi : g_q_hi;
    __nv_bfloat16* __restrict__ Clo = is_k ? g_k_lo : g_q_lo;

    const int tid = threadIdx.x;
    const int lane = tid & 31;
    const int wid = tid >> 5;
    const int wm = wid & 3;
    const int wn = wid >> 2;
    const int m0 = blockIdx.x * 128;
    const int n0 = blockIdx.y * 128;
    const unsigned sbase = sm_u32(smem_raw);

    float acc[2][8][4];
#pragma unroll
    for (int mt = 0; mt < 2; mt++)
#pragma unroll
        for (int nt = 0; nt < 8; nt++)
#pragma unroll
            for (int i = 0; i < 4; i++) acc[mt][nt][i] = 0.f;

    float4 ra[4], rb[4];

#pragma unroll
    for (int l = 0; l < 4; l++) {
        int f = tid + l * 256;
        int row = f >> 3, c4 = f & 7;
        ra[l] = *(const float4*)(X + (size_t)(m0 + row) * D + c4 * 4);
        rb[l] = *(const float4*)(W + (size_t)(n0 + row) * D + c4 * 4);
    }
#pragma unroll
    for (int l = 0; l < 4; l++) {
        int f = tid + l * 256;
        int row = f >> 3, c4 = f & 7;
        unsigned h0, l0, h1, l1;
        split_pack(ra[l].x, ra[l].y, h0, l0);
        split_pack(ra[l].z, ra[l].w, h1, l1);
        *(uint2*)(smem_raw + PJ_AHI + row * 80 + c4 * 8) = make_uint2(h0, h1);
        *(uint2*)(smem_raw + PJ_ALO + row * 80 + c4 * 8) = make_uint2(l0, l1);
        split_pack(rb[l].x, rb[l].y, h0, l0);
        split_pack(rb[l].z, rb[l].w, h1, l1);
        *(uint2*)(smem_raw + PJ_BHI + row * 80 + c4 * 8) = make_uint2(h0, h1);
        *(uint2*)(smem_raw + PJ_BLO + row * 80 + c4 * 8) = make_uint2(l0, l1);
    }
    __syncthreads();

    for (int c = 0; c < 32; c++) {
        if (c < 31) {
            int k0 = (c + 1) * 32;
#pragma unroll
            for (int l = 0; l < 4; l++) {
                int f = tid + l * 256;
                int row = f >> 3, c4 = f & 7;
                ra[l] = *(const float4*)(X + (size_t)(m0 + row) * D + k0 + c4 * 4);
                rb[l] = *(const float4*)(W + (size_t)(n0 + row) * D + k0 + c4 * 4);
            }
        }
        {
            const unsigned base = sbase + (c & 1) * PJ_BUF;
#pragma unroll
            for (int kk = 0; kk < 2; kk++) {
                unsigned ahi[2][4], alo[2][4];
#pragma unroll
                for (int mt = 0; mt < 2; mt++) {
                    unsigned rbytes = (unsigned)(wm * 32 + mt * 16 + (lane & 7) + ((lane >> 3) & 1) * 8) * 80
                                    + ((lane >> 4) & 1) * 16 + kk * 32;
                    ldsm4(ahi[mt], base + PJ_AHI + rbytes);
                    ldsm4(alo[mt], base + PJ_ALO + rbytes);
                }
#pragma unroll
                for (int nt2 = 0; nt2 < 4; nt2++) {
                    unsigned rbytes = (unsigned)(wn * 64 + nt2 * 16 + (lane & 7) + ((lane >> 4) & 1) * 8) * 80
                                    + ((lane >> 3) & 1) * 16 + kk * 32;
                    unsigned bhi[4], blo[4];
                    ldsm4(bhi, base + PJ_BHI + rbytes);
                    ldsm4(blo, base + PJ_BLO + rbytes);
#pragma unroll
                    for (int mt = 0; mt < 2; mt++) {
                        mma16816(acc[mt][nt2 * 2],     ahi[mt], bhi);
                        mma16816(acc[mt][nt2 * 2 + 1], ahi[mt], bhi + 2);
                        mma16816(acc[mt][nt2 * 2],     ahi[mt], blo);
                        mma16816(acc[mt][nt2 * 2 + 1], ahi[mt], blo + 2);
                        mma16816(acc[mt][nt2 * 2],     alo[mt], bhi);
                        mma16816(acc[mt][nt2 * 2 + 1], alo[mt], bhi + 2);
                    }
                }
            }
        }
        if (c < 31) {
            char* dst = smem_raw + ((c + 1) & 1) * PJ_BUF;
#pragma unroll
            for (int l = 0; l < 4; l++) {
                int f = tid + l * 256;
                int row = f >> 3, c4 = f & 7;
                unsigned h0, l0, h1, l1;
                split_pack(ra[l].x, ra[l].y, h0, l0);
                split_pack(ra[l].z, ra[l].w, h1, l1);
                *(uint2*)(dst + PJ_AHI + row * 80 + c4 * 8) = make_uint2(h0, h1);
                *(uint2*)(dst + PJ_ALO + row * 80 + c4 * 8) = make_uint2(l0, l1);
                split_pack(rb[l].x, rb[l].y, h0, l0);
                split_pack(rb[l].z, rb[l].w, h1, l1);
                *(uint2*)(dst + PJ_BHI + row * 80 + c4 * 8) = make_uint2(h0, h1);
                *(uint2*)(dst + PJ_BLO + row * 80 + c4 * 8) = make_uint2(l0, l1);
            }
            __syncthreads();
        }
    }

    const int q = lane >> 2, tig = lane & 3;
#pragma unroll
    for (int mt = 0; mt < 2; mt++) {
#pragma unroll
        for (int nt = 0; nt < 8; nt++) {
            int col = n0 + wn * 64 + nt * 8 + tig * 2;
            float2 bb = *(const float2*)(bias + col);
            int row = m0 + wm * 32 + mt * 16 + q;
            unsigned hi, lo;
            split_pack(acc[mt][nt][0] + bb.x, acc[mt][nt][1] + bb.y, hi, lo);
            *reinterpret_cast<unsigned*>(&Chi[(size_t)row * D + col]) = hi;
            *reinterpret_cast<unsigned*>(&Clo[(size_t)row * D + col]) = lo;
            split_pack(acc[mt][nt][2] + bb.x, acc[mt][nt][3] + bb.y, hi, lo);
            *reinterpret_cast<unsigned*>(&Chi[(size_t)(row + 8) * D + col]) = hi;
            *reinterpret_cast<unsigned*>(&Clo[(size_t)(row + 8) * D + col]) = lo;
        }
    }
}

// ---------------------------------------------------------------------------
// Kernel 2: aspect path (round-3 verbatim).
// ---------------------------------------------------------------------------
__global__ __launch_bounds__(256) void aspect_kernel(
    const float* __restrict__ aspect, const float* __restrict__ Wd, const float* __restrict__ bd,
    const float* __restrict__ wm, const float* __restrict__ bm)
{
    const int bh = blockIdx.x;
    const int b = bh >> 4;
    const int h = bh & 15;
    const int tid = threadIdx.x;

    __shared__ float asp_s[64];
    __shared__ float aw_s[64];

    {
        int e = tid >> 2, p = tid & 3;
        const float* av = aspect + (size_t)b * D + p * 256;
        const float* wv = Wd + (size_t)e * D + p * 256;
        float sum = 0.f;
#pragma unroll 4
        for (int d = 0; d < 256; d += 4) {
            float4 a = *(const float4*)(av + d);
            float4 w = *(const float4*)(wv + d);
            sum += a.x * w.x + a.y * w.y + a.z * w.z + a.w * w.w;
        }
        sum += __shfl_xor_sync(0xffffffffu, sum, 1, 4);
        sum += __shfl_xor_sync(0xffffffffu, sum, 2, 4);
        if (p == 0) asp_s[e] = sum + bd[e];
    }
    __syncthreads();
    if (tid < 64) {
        float s = 0.f;
        const float* w = wm + (size_t)h * DK * DK + tid;
#pragma unroll 8
        for (int c = 0; c < 64; c++) s += asp_s[c] * w[c * 64];
        aw_s[tid] = s;
    }
    __syncthreads();
    const float bias = bm[0];
    for (int j = tid; j < S; j += 256) {
        const __nv_bfloat162* kh =
            reinterpret_cast<const __nv_bfloat162*>(g_k_hi + ((size_t)b * S + j) * D + h * DK);
        const __nv_bfloat162* kl =
            reinterpret_cast<const __nv_bfloat162*>(g_k_lo + ((size_t)b * S + j) * D + h * DK);
        float s = 0.f;
#pragma unroll
        for (int d2 = 0; d2 < 32; d2++) {
            float2 a = __bfloat1622float2(kh[d2]);
            float2 c = __bfloat1622float2(kl[d2]);
            s += aw_s[2 * d2] * (a.x + c.x) + aw_s[2 * d2 + 1] * (a.y + c.y);
        }
        float x = s + bias;
        float t = 1.f - 2.f / (__expf(2.f * x) + 1.f);
        g_asco[(size_t)bh * S + j] = t;
    }
}

// ---------------------------------------------------------------------------
// Kernel 3 (round-9 measured 270.5us): fused scores + softmax, v1 structure
// + packed-mask cp.async staging (lands free during the mma phase).
// ---------------------------------------------------------------------------
#define SC_SQHI 0
#define SC_SQLO 4608
#define SC_ASCS 9216
#define SC_REDM 13312
#define SC_REDS 15488
#define SC_REDM2 17664
#define SC_REDS2 17792
#define SC_SKHI 17920
#define SC_SKLO 99840
#define SC_MASK 181760
#define SC_TOTAL (SC_MASK + 32 * 1040)   // 215040

__global__ void __launch_bounds__(512, 1) scores_kernel(
    const float* __restrict__ shortp, float* __restrict__ out)
{
    extern __shared__ char smem_raw[];
    const int b = blockIdx.z;
    const int h = blockIdx.y;
    const int m0 = blockIdx.x * 32;
    const int bh = b * H + h;
    const int tid = threadIdx.x;
    const int lane = tid & 31;
    const int wid = tid >> 5;
    const unsigned sbase = sm_u32(smem_raw);

    // ---- stage mask bytes (32 rows x 1024) via cp.async; lands during mma ----
#pragma unroll
    for (int l = 0; l < 4; l++) {
        int f = tid + l * 512;
        int row = f >> 6, g = f & 63;
        cpa16(sbase + SC_MASK + row * 1040 + g * 16,
              g_mask8 + ((size_t)(b * S) + m0 + row) * S + g * 16);
    }
    CP_COMMIT();

    {
        int row = tid >> 4, g = tid & 15;
        size_t goff = ((size_t)(b * S) + m0 + row) * D + h * DK + g * 4;
        *(uint2*)(smem_raw + SC_SQHI + row * 144 + g * 8) = *(const uint2*)(g_q_hi + goff);
        *(uint2*)(smem_raw + SC_SQLO + row * 144 + g * 8) = *(const uint2*)(g_q_lo + goff);
    }
    ((float2*)(smem_raw + SC_ASCS))[tid] = *(const float2*)(g_asco + (size_t)bh * S + tid * 2);

    float acc[2][8][4];
#pragma unroll
    for (int mt = 0; mt < 2; mt++)
#pragma unroll
        for (int nt = 0; nt < 8; nt++)
#pragma unroll
            for (int i = 0; i < 4; i++) acc[mt][nt][i] = 0.f;

    for (int chunk = 0; chunk < 2; chunk++) {
        if (chunk) __syncthreads();
#pragma unroll
        for (int l = 0; l < 8; l++) {
            int f = tid + l * 512;
            int row = f >> 2, g = f & 3;
            size_t goff = ((size_t)(b * S) + row) * D + h * DK + chunk * 32 + g * 8;
            *(uint4*)(smem_raw + SC_SKHI + row * 80 + g * 16) = *(const uint4*)(g_k_hi + goff);
            *(uint4*)(smem_raw + SC_SKLO + row * 80 + g * 16) = *(const uint4*)(g_k_lo + goff);
        }
        __syncthreads();

#pragma unroll
        for (int kk2 = 0; kk2 < 2; kk2++) {
            const int kglob = chunk * 2 + kk2;
            unsigned ahi[2][4], alo[2][4];
#pragma unroll
            for (int mt = 0; mt < 2; mt++) {
                unsigned rbytes = (unsigned)(mt * 16 + (lane & 7) + ((lane >> 3) & 1) * 8) * 144
                                + ((lane >> 4) & 1) * 16 + kglob * 32;
                ldsm4(ahi[mt], sbase + SC_SQHI + rbytes);
                ldsm4(alo[mt], sbase + SC_SQLO + rbytes);
            }
#pragma unroll
            for (int nt2 = 0; nt2 < 4; nt2++) {
                unsigned rbytes = (unsigned)(wid * 64 + nt2 * 16 + (lane & 7) + ((lane >> 4) & 1) * 8) * 80
                                + ((lane >> 3) & 1) * 16 + kk2 * 32;
                unsigned bhi[4], blo[4];
                ldsm4(bhi, sbase + SC_SKHI + rbytes);
                ldsm4(blo, sbase + SC_SKLO + rbytes);
#pragma unroll
                for (int mt = 0; mt < 2; mt++) {
                    mma16816(acc[mt][nt2 * 2],     ahi[mt], bhi);
                    mma16816(acc[mt][nt2 * 2 + 1], ahi[mt], bhi + 2);
                    mma16816(acc[mt][nt2 * 2],     ahi[mt], blo);
                    mma16816(acc[mt][nt2 * 2 + 1], ahi[mt], blo + 2);
                    mma16816(acc[mt][nt2 * 2],     alo[mt], bhi);
                    mma16816(acc[mt][nt2 * 2 + 1], alo[mt], bhi + 2);
                }
            }
        }
    }

    CP_WAIT(0);
    __syncthreads();

    // ---- fused epilogue: /8 + asco + short, mask (smem bytes), softmax ----
    const int q = lane >> 2, tig = lane & 3;
    const float* ascf = (const float*)(smem_raw + SC_ASCS);
    float* redM = (float*)(smem_raw + SC_REDM);
    float* redS = (float*)(smem_raw + SC_REDS);
    float* redM2 = (float*)(smem_raw + SC_REDM2);
    float* redS2 = (float*)(smem_raw + SC_REDS2);

#pragma unroll
    for (int mt = 0; mt < 2; mt++) {
#pragma unroll
        for (int hf = 0; hf < 2; hf++) {
            int rl = mt * 16 + hf * 8 + q;
            int grow = m0 + rl;
            const float* shp = shortp + ((size_t)bh * S + grow) * S + wid * 64 + tig * 2;
            const unsigned char* mrow =
                (const unsigned char*)(smem_raw + SC_MASK + rl * 1040 + wid * 64 + tig * 2);
            float mx = -1e30f;
#pragma unroll
            for (int nt = 0; nt < 8; nt++) {
                float2 sh = *(const float2*)(shp + nt * 8);
                uchar2 mk = *(const uchar2*)(mrow + nt * 8);
                int ci = wid * 64 + nt * 8 + tig * 2;
                float s0 = acc[mt][nt][hf * 2]     * 0.125f + ascf[ci]     + sh.x;
                float s1 = acc[mt][nt][hf * 2 + 1] * 0.125f + ascf[ci + 1] + sh.y;
                s0 = mk.x ? s0 : -1e9f;
                s1 = mk.y ? s1 : -1e9f;
                acc[mt][nt][hf * 2] = s0;
                acc[mt][nt][hf * 2 + 1] = s1;
                mx = fmaxf(mx, fmaxf(s0, s1));
            }
            mx = fmaxf(mx, __shfl_xor_sync(0xffffffffu, mx, 1));
            mx = fmaxf(mx, __shfl_xor_sync(0xffffffffu, mx, 2));
            if (tig == 0) redM[rl * 17 + wid] = mx;
        }
    }
    __syncthreads();
    if (tid < 32) {
        float m = redM[tid * 17];
#pragma unroll
        for (int w = 1; w < 16; w++) m = fmaxf(m, redM[tid * 17 + w]);
        redM2[tid] = m;
    }
    __syncthreads();

#pragma unroll
    for (int mt = 0; mt < 2; mt++) {
#pragma unroll
        for (int hf = 0; hf < 2; hf++) {
            int rl = mt * 16 + hf * 8 + q;
            float m = redM2[rl];
            float sum = 0.f;
#pragma unroll
            for (int nt = 0; nt < 8; nt++) {
                float e0 = __expf(acc[mt][nt][hf * 2] - m);
                float e1 = __expf(acc[mt][nt][hf * 2 + 1] - m);
                acc[mt][nt][hf * 2] = e0;
                acc[mt][nt][hf * 2 + 1] = e1;
                sum += e0 + e1;
            }
            sum += __shfl_xor_sync(0xffffffffu, sum, 1);
            sum += __shfl_xor_sync(0xffffffffu, sum, 2);
            if (tig == 0) redS[rl * 17 + wid] = sum;
        }
    }
    __syncthreads();
    if (tid < 32) {
        float s = 0.f;
#pragma unroll
        for (int w = 0; w < 16; w++) s += redS[tid * 17 + w];
        redS2[tid] = s;
    }
    __syncthreads();

#pragma unroll
    for (int mt = 0; mt < 2; mt++) {
#pragma unroll
        for (int hf = 0; hf < 2; hf++) {
            int rl = mt * 16 + hf * 8 + q;
            int grow = m0 + rl;
            float inv = 1.0f / redS2[rl];
            float* op = out + ((size_t)bh * S + grow) * S + wid * 64 + tig * 2;
#pragma unroll
            for (int nt = 0; nt < 8; nt++) {
                float2 o;
                o.x = acc[mt][nt][hf * 2] * inv;
                o.y = acc[mt][nt][hf * 2 + 1] * inv;
                *(float2*)(op + nt * 8) = o;
            }
        }
    }
}

// ---------------------------------------------------------------------------
extern "C" void kernel_launch(void* const* d_in, const int* in_sizes, int n_in,
                              void* d_out, int out_size)
{
    const float* query  = (const float*)d_in[0];
    const float* key    = (const float*)d_in[1];
    const int*   mask   = (const int*)  d_in[2];
    const float* aspect = (const float*)d_in[3];
    const float* shortp = (const float*)d_in[4];
    const float* Wq     = (const float*)d_in[5];
    const float* bq     = (const float*)d_in[6];
    const float* Wk     = (const float*)d_in[7];
    const float* bk     = (const float*)d_in[8];
    const float* Wd     = (const float*)d_in[9];
    const float* bd     = (const float*)d_in[10];
    const float* wm     = (const float*)d_in[11];
    const float* bm     = (const float*)d_in[12];
    float* out = (float*)d_out;

    cudaFuncSetAttribute(proj_kernel, cudaFuncAttributeMaxDynamicSharedMemorySize, 2 * PJ_BUF);
    cudaFuncSetAttribute(scores_kernel, cudaFuncAttributeMaxDynamicSharedMemorySize, SC_TOTAL);

    unsigned char* mask8;
    cudaGetSymbolAddress((void**)&mask8, g_mask8);

    const int nM4 = BATCH * S * S / 4;
    mask8_kernel<<<nM4 / 256, 256>>>(mask, mask8, nM4);

    dim3 gp(32, 8, 2);                      // M tiles, N tiles, {Q,K}
    proj_kernel<<<gp, 256, 2 * PJ_BUF>>>(query, Wq, bq, key, Wk, bk);

    aspect_kernel<<<BATCH * H, 256>>>(aspect, Wd, bd, wm, bm);

    dim3 gs(S / 32, H, BATCH);
    scores_kernel<<<gs, 512, SC_TOTAL>>>(shortp, out);
}

// round 11
// speedup vs baseline: 1.0268x; 1.0268x over previous
#include <cuda_runtime.h>
#include <cuda_bf16.h>

#define BATCH 4
#define S 1024
#define D 1024
#define H 16
#define DK 64

// ---------------------------------------------------------------------------
// scratch (allocation-free: __device__ globals), split bf16: v ~= hi + lo
// ---------------------------------------------------------------------------
__device__ __nv_bfloat16 g_q_hi[BATCH * S * D];
__device__ __nv_bfloat16 g_q_lo[BATCH * S * D];
__device__ __nv_bfloat16 g_k_hi[BATCH * S * D];
__device__ __nv_bfloat16 g_k_lo[BATCH * S * D];
__device__ float g_asco[BATCH * H * S];
__device__ float g_aw[BATCH * H * DK];             // aspect @ Wd @ weight_m
__device__ unsigned char g_mask8[BATCH * S * S];   // packed mask bytes

// ---------------------------------------------------------------------------
// helpers
// ---------------------------------------------------------------------------
__device__ __forceinline__ unsigned sm_u32(const void* p) {
    return (unsigned)__cvta_generic_to_shared(p);
}

__device__ __forceinline__ void ldsm4(unsigned r[4], unsigned addr) {
    asm volatile("ldmatrix.sync.aligned.m8n8.x4.shared.b16 {%0,%1,%2,%3}, [%4];"
                 : "=r"(r[0]), "=r"(r[1]), "=r"(r[2]), "=r"(r[3])
                 : "r"(addr));
}

__device__ __forceinline__ void mma16816(float* c, const unsigned* a, const unsigned* b) {
    asm volatile(
        "mma.sync.aligned.m16n8k16.row.col.f32.bf16.bf16.f32 "
        "{%0,%1,%2,%3}, {%4,%5,%6,%7}, {%8,%9}, {%0,%1,%2,%3};"
        : "+f"(c[0]), "+f"(c[1]), "+f"(c[2]), "+f"(c[3])
        : "r"(a[0]), "r"(a[1]), "r"(a[2]), "r"(a[3]), "r"(b[0]), "r"(b[1]));
}

__device__ __forceinline__ void split_pack(float x, float y, unsigned& hi, unsigned& lo) {
    __nv_bfloat162 h, l;
    h.x = __float2bfloat16(x);
    h.y = __float2bfloat16(y);
    l.x = __float2bfloat16(x - __bfloat162float(h.x));
    l.y = __float2bfloat16(y - __bfloat162float(h.y));
    hi = *reinterpret_cast<unsigned*>(&h);
    lo = *reinterpret_cast<unsigned*>(&l);
}

__device__ __forceinline__ void cpa16(unsigned dst, const void* src) {
    asm volatile("cp.async.cg.shared.global [%0], [%1], 16;" :: "r"(dst), "l"(src));
}
#define CP_COMMIT() asm volatile("cp.async.commit_group;")
#define CP_WAIT(N)  asm volatile("cp.async.wait_group %0;" :: "n"(N))

// ---------------------------------------------------------------------------
// Kernel 0: pack mask int32 {0,1} -> uint8 (exact).
// ---------------------------------------------------------------------------
__global__ __launch_bounds__(256) void mask8_kernel(
    const int* __restrict__ m, unsigned char* __restrict__ o, int n4)
{
    int i = blockIdx.x * 256 + threadIdx.x;
    if (i < n4) {
        int4 v = ((const int4*)m)[i];
        uchar4 u;
        u.x = (unsigned char)v.x; u.y = (unsigned char)v.y;
        u.z = (unsigned char)v.z; u.w = (unsigned char)v.w;
        ((uchar4*)o)[i] = u;
    }
}

// ---------------------------------------------------------------------------
// Kernel 1 (round-3 proven, 183us): C = X @ W^T + bias, z in {Q, K}.
// 128x128 CTA tile, BK=32, double-buffered smem, inline fp32->hi/lo convert,
// 3-term split-bf16 mma, 8 warps, warp tile 32x64.
// ---------------------------------------------------------------------------
#define PJ_AHI 0
#define PJ_ALO 10240
#define PJ_BHI 20480
#define PJ_BLO 30720
#define PJ_BUF 40960

__global__ void __launch_bounds__(256, 1) proj_kernel(
    const float* __restrict__ Xq, const float* __restrict__ Wq, const float* __restrict__ bq,
    const float* __restrict__ Xk, const float* __restrict__ Wk, const float* __restrict__ bk)
{
    extern __shared__ char smem_raw[];
    const bool is_k = blockIdx.z != 0;
    const float* __restrict__ X = is_k ? Xk : Xq;
    const float* __restrict__ W = is_k ? Wk : Wq;
    const float* __restrict__ bias = is_k ? bk : bq;
    __nv_bfloat16* __restrict__ Chi = is_k ? g_k_hi : g_q_hi;
    __nv_bfloat16* __restrict__ Clo = is_k ? g_k_lo : g_q_lo;

    const int tid = threadIdx.x;
    const int lane = tid & 31;
    const int wid = tid >> 5;
    const int wm = wid & 3;
    const int wn = wid >> 2;
    const int m0 = blockIdx.x * 128;
    const int n0 = blockIdx.y * 128;
    const unsigned sbase = sm_u32(smem_raw);

    float acc[2][8][4];
#pragma unroll
    for (int mt = 0; mt < 2; mt++)
#pragma unroll
        for (int nt = 0; nt < 8; nt++)
#pragma unroll
            for (int i = 0; i < 4; i++) acc[mt][nt][i] = 0.f;

    float4 ra[4], rb[4];

#pragma unroll
    for (int l = 0; l < 4; l++) {
        int f = tid + l * 256;
        int row = f >> 3, c4 = f & 7;
        ra[l] = *(const float4*)(X + (size_t)(m0 + row) * D + c4 * 4);
        rb[l] = *(const float4*)(W + (size_t)(n0 + row) * D + c4 * 4);
    }
#pragma unroll
    for (int l = 0; l < 4; l++) {
        int f = tid + l * 256;
        int row = f >> 3, c4 = f & 7;
        unsigned h0, l0, h1, l1;
        split_pack(ra[l].x, ra[l].y, h0, l0);
        split_pack(ra[l].z, ra[l].w, h1, l1);
        *(uint2*)(smem_raw + PJ_AHI + row * 80 + c4 * 8) = make_uint2(h0, h1);
        *(uint2*)(smem_raw + PJ_ALO + row * 80 + c4 * 8) = make_uint2(l0, l1);
        split_pack(rb[l].x, rb[l].y, h0, l0);
        split_pack(rb[l].z, rb[l].w, h1, l1);
        *(uint2*)(smem_raw + PJ_BHI + row * 80 + c4 * 8) = make_uint2(h0, h1);
        *(uint2*)(smem_raw + PJ_BLO + row * 80 + c4 * 8) = make_uint2(l0, l1);
    }
    __syncthreads();

    for (int c = 0; c < 32; c++) {
        if (c < 31) {
            int k0 = (c + 1) * 32;
#pragma unroll
            for (int l = 0; l < 4; l++) {
                int f = tid + l * 256;
                int row = f >> 3, c4 = f & 7;
                ra[l] = *(const float4*)(X + (size_t)(m0 + row) * D + k0 + c4 * 4);
                rb[l] = *(const float4*)(W + (size_t)(n0 + row) * D + k0 + c4 * 4);
            }
        }
        {
            const unsigned base = sbase + (c & 1) * PJ_BUF;
#pragma unroll
            for (int kk = 0; kk < 2; kk++) {
                unsigned ahi[2][4], alo[2][4];
#pragma unroll
                for (int mt = 0; mt < 2; mt++) {
                    unsigned rbytes = (unsigned)(wm * 32 + mt * 16 + (lane & 7) + ((lane >> 3) & 1) * 8) * 80
                                    + ((lane >> 4) & 1) * 16 + kk * 32;
                    ldsm4(ahi[mt], base + PJ_AHI + rbytes);
                    ldsm4(alo[mt], base + PJ_ALO + rbytes);
                }
#pragma unroll
                for (int nt2 = 0; nt2 < 4; nt2++) {
                    unsigned rbytes = (unsigned)(wn * 64 + nt2 * 16 + (lane & 7) + ((lane >> 4) & 1) * 8) * 80
                                    + ((lane >> 3) & 1) * 16 + kk * 32;
                    unsigned bhi[4], blo[4];
                    ldsm4(bhi, base + PJ_BHI + rbytes);
                    ldsm4(blo, base + PJ_BLO + rbytes);
#pragma unroll
                    for (int mt = 0; mt < 2; mt++) {
                        mma16816(acc[mt][nt2 * 2],     ahi[mt], bhi);
                        mma16816(acc[mt][nt2 * 2 + 1], ahi[mt], bhi + 2);
                        mma16816(acc[mt][nt2 * 2],     ahi[mt], blo);
                        mma16816(acc[mt][nt2 * 2 + 1], ahi[mt], blo + 2);
                        mma16816(acc[mt][nt2 * 2],     alo[mt], bhi);
                        mma16816(acc[mt][nt2 * 2 + 1], alo[mt], bhi + 2);
                    }
                }
            }
        }
        if (c < 31) {
            char* dst = smem_raw + ((c + 1) & 1) * PJ_BUF;
#pragma unroll
            for (int l = 0; l < 4; l++) {
                int f = tid + l * 256;
                int row = f >> 3, c4 = f & 7;
                unsigned h0, l0, h1, l1;
                split_pack(ra[l].x, ra[l].y, h0, l0);
                split_pack(ra[l].z, ra[l].w, h1, l1);
                *(uint2*)(dst + PJ_AHI + row * 80 + c4 * 8) = make_uint2(h0, h1);
                *(uint2*)(dst + PJ_ALO + row * 80 + c4 * 8) = make_uint2(l0, l1);
                split_pack(rb[l].x, rb[l].y, h0, l0);
                split_pack(rb[l].z, rb[l].w, h1, l1);
                *(uint2*)(dst + PJ_BHI + row * 80 + c4 * 8) = make_uint2(h0, h1);
                *(uint2*)(dst + PJ_BLO + row * 80 + c4 * 8) = make_uint2(l0, l1);
            }
            __syncthreads();
        }
    }

    const int q = lane >> 2, tig = lane & 3;
#pragma unroll
    for (int mt = 0; mt < 2; mt++) {
#pragma unroll
        for (int nt = 0; nt < 8; nt++) {
            int col = n0 + wn * 64 + nt * 8 + tig * 2;
            float2 bb = *(const float2*)(bias + col);
            int row = m0 + wm * 32 + mt * 16 + q;
            unsigned hi, lo;
            split_pack(acc[mt][nt][0] + bb.x, acc[mt][nt][1] + bb.y, hi, lo);
            *reinterpret_cast<unsigned*>(&Chi[(size_t)row * D + col]) = hi;
            *reinterpret_cast<unsigned*>(&Clo[(size_t)row * D + col]) = lo;
            split_pack(acc[mt][nt][2] + bb.x, acc[mt][nt][3] + bb.y, hi, lo);
            *reinterpret_cast<unsigned*>(&Chi[(size_t)(row + 8) * D + col]) = hi;
            *reinterpret_cast<unsigned*>(&Clo[(size_t)(row + 8) * D + col]) = lo;
        }
    }
}

// ---------------------------------------------------------------------------
// Kernel 2a: aspect stage 1 — aw[b,h,:] = (aspect[b] @ Wd^T + bd) @ wm[h].
// 64 CTAs, tiny; writes 16KB to global.
// ---------------------------------------------------------------------------
__global__ __launch_bounds__(256) void aspect1_kernel(
    const float* __restrict__ aspect, const float* __restrict__ Wd, const float* __restrict__ bd,
    const float* __restrict__ wm)
{
    const int bh = blockIdx.x;
    const int b = bh >> 4;
    const int h = bh & 15;
    const int tid = threadIdx.x;

    __shared__ float asp_s[64];

    {
        int e = tid >> 2, p = tid & 3;
        const float* av = aspect + (size_t)b * D + p * 256;
        const float* wv = Wd + (size_t)e * D + p * 256;
        float sum = 0.f;
#pragma unroll 4
        for (int d = 0; d < 256; d += 4) {
            float4 a = *(const float4*)(av + d);
            float4 w = *(const float4*)(wv + d);
            sum += a.x * w.x + a.y * w.y + a.z * w.z + a.w * w.w;
        }
        sum += __shfl_xor_sync(0xffffffffu, sum, 1, 4);
        sum += __shfl_xor_sync(0xffffffffu, sum, 2, 4);
        if (p == 0) asp_s[e] = sum + bd[e];
    }
    __syncthreads();
    if (tid < 64) {
        float s = 0.f;
        const float* w = wm + (size_t)h * DK * DK + tid;
#pragma unroll 8
        for (int c = 0; c < 64; c++) s += asp_s[c] * w[c * 64];
        g_aw[bh * DK + tid] = s;
    }
}

// ---------------------------------------------------------------------------
// Kernel 2b: aspect stage 2 — asco[b,h,j] = tanh(aw[b,h] . k[b,h,j] + bias_m).
// grid (8, B*H) x 128 threads: one j per thread, full-chip parallel.
// ---------------------------------------------------------------------------
__global__ __launch_bounds__(128) void aspect2_kernel(const float* __restrict__ bm)
{
    const int bh = blockIdx.y;
    const int b = bh >> 4;
    const int h = bh & 15;
    const int tid = threadIdx.x;
    const int j = blockIdx.x * 128 + tid;

    __shared__ float aw_s[64];
    if (tid < 64) aw_s[tid] = g_aw[bh * DK + tid];
    __syncthreads();

    const __nv_bfloat162* kh =
        reinterpret_cast<const __nv_bfloat162*>(g_k_hi + ((size_t)b * S + j) * D + h * DK);
    const __nv_bfloat162* kl =
        reinterpret_cast<const __nv_bfloat162*>(g_k_lo + ((size_t)b * S + j) * D + h * DK);
    float s = 0.f;
#pragma unroll
    for (int d2 = 0; d2 < 32; d2++) {
        float2 a = __bfloat1622float2(kh[d2]);
        float2 c = __bfloat1622float2(kl[d2]);
        s += aw_s[2 * d2] * (a.x + c.x) + aw_s[2 * d2 + 1] * (a.y + c.y);
    }
    float x = s + bm[0];
    float t = 1.f - 2.f / (__expf(2.f * x) + 1.f);
    g_asco[(size_t)bh * S + j] = t;
}

// ---------------------------------------------------------------------------
// Kernel 3 (measured 268.9us): fused scores + softmax, v1 structure
// + packed-mask cp.async staging.
// ---------------------------------------------------------------------------
#define SC_SQHI 0
#define SC_SQLO 4608
#define SC_ASCS 9216
#define SC_REDM 13312
#define SC_REDS 15488
#define SC_REDM2 17664
#define SC_REDS2 17792
#define SC_SKHI 17920
#define SC_SKLO 99840
#define SC_MASK 181760
#define SC_TOTAL (SC_MASK + 32 * 1040)   // 215040

__global__ void __launch_bounds__(512, 1) scores_kernel(
    const float* __restrict__ shortp, float* __restrict__ out)
{
    extern __shared__ char smem_raw[];
    const int b = blockIdx.z;
    const int h = blockIdx.y;
    const int m0 = blockIdx.x * 32;
    const int bh = b * H + h;
    const int tid = threadIdx.x;
    const int lane = tid & 31;
    const int wid = tid >> 5;
    const unsigned sbase = sm_u32(smem_raw);

    // ---- stage mask bytes (32 rows x 1024) via cp.async; lands during mma ----
#pragma unroll
    for (int l = 0; l < 4; l++) {
        int f = tid + l * 512;
        int row = f >> 6, g = f & 63;
        cpa16(sbase + SC_MASK + row * 1040 + g * 16,
              g_mask8 + ((size_t)(b * S) + m0 + row) * S + g * 16);
    }
    CP_COMMIT();

    {
        int row = tid >> 4, g = tid & 15;
        size_t goff = ((size_t)(b * S) + m0 + row) * D + h * DK + g * 4;
        *(uint2*)(smem_raw + SC_SQHI + row * 144 + g * 8) = *(const uint2*)(g_q_hi + goff);
        *(uint2*)(smem_raw + SC_SQLO + row * 144 + g * 8) = *(const uint2*)(g_q_lo + goff);
    }
    ((float2*)(smem_raw + SC_ASCS))[tid] = *(const float2*)(g_asco + (size_t)bh * S + tid * 2);

    float acc[2][8][4];
#pragma unroll
    for (int mt = 0; mt < 2; mt++)
#pragma unroll
        for (int nt = 0; nt < 8; nt++)
#pragma unroll
            for (int i = 0; i < 4; i++) acc[mt][nt][i] = 0.f;

    for (int chunk = 0; chunk < 2; chunk++) {
        if (chunk) __syncthreads();
#pragma unroll
        for (int l = 0; l < 8; l++) {
            int f = tid + l * 512;
            int row = f >> 2, g = f & 3;
            size_t goff = ((size_t)(b * S) + row) * D + h * DK + chunk * 32 + g * 8;
            *(uint4*)(smem_raw + SC_SKHI + row * 80 + g * 16) = *(const uint4*)(g_k_hi + goff);
            *(uint4*)(smem_raw + SC_SKLO + row * 80 + g * 16) = *(const uint4*)(g_k_lo + goff);
        }
        __syncthreads();

#pragma unroll
        for (int kk2 = 0; kk2 < 2; kk2++) {
            const int kglob = chunk * 2 + kk2;
            unsigned ahi[2][4], alo[2][4];
#pragma unroll
            for (int mt = 0; mt < 2; mt++) {
                unsigned rbytes = (unsigned)(mt * 16 + (lane & 7) + ((lane >> 3) & 1) * 8) * 144
                                + ((lane >> 4) & 1) * 16 + kglob * 32;
                ldsm4(ahi[mt], sbase + SC_SQHI + rbytes);
                ldsm4(alo[mt], sbase + SC_SQLO + rbytes);
            }
#pragma unroll
            for (int nt2 = 0; nt2 < 4; nt2++) {
                unsigned rbytes = (unsigned)(wid * 64 + nt2 * 16 + (lane & 7) + ((lane >> 4) & 1) * 8) * 80
                                + ((lane >> 3) & 1) * 16 + kk2 * 32;
                unsigned bhi[4], blo[4];
                ldsm4(bhi, sbase + SC_SKHI + rbytes);
                ldsm4(blo, sbase + SC_SKLO + rbytes);
#pragma unroll
                for (int mt = 0; mt < 2; mt++) {
                    mma16816(acc[mt][nt2 * 2],     ahi[mt], bhi);
                    mma16816(acc[mt][nt2 * 2 + 1], ahi[mt], bhi + 2);
                    mma16816(acc[mt][nt2 * 2],     ahi[mt], blo);
                    mma16816(acc[mt][nt2 * 2 + 1], ahi[mt], blo + 2);
                    mma16816(acc[mt][nt2 * 2],     alo[mt], bhi);
                    mma16816(acc[mt][nt2 * 2 + 1], alo[mt], bhi + 2);
                }
            }
        }
    }

    CP_WAIT(0);
    __syncthreads();

    // ---- fused epilogue: /8 + asco + short, mask (smem bytes), softmax ----
    const int q = lane >> 2, tig = lane & 3;
    const float* ascf = (const float*)(smem_raw + SC_ASCS);
    float* redM = (float*)(smem_raw + SC_REDM);
    float* redS = (float*)(smem_raw + SC_REDS);
    float* redM2 = (float*)(smem_raw + SC_REDM2);
    float* redS2 = (float*)(smem_raw + SC_REDS2);

#pragma unroll
    for (int mt = 0; mt < 2; mt++) {
#pragma unroll
        for (int hf = 0; hf < 2; hf++) {
            int rl = mt * 16 + hf * 8 + q;
            int grow = m0 + rl;
            const float* shp = shortp + ((size_t)bh * S + grow) * S + wid * 64 + tig * 2;
            const unsigned char* mrow =
                (const unsigned char*)(smem_raw + SC_MASK + rl * 1040 + wid * 64 + tig * 2);
            float mx = -1e30f;
#pragma unroll
            for (int nt = 0; nt < 8; nt++) {
                float2 sh = *(const float2*)(shp + nt * 8);
                uchar2 mk = *(const uchar2*)(mrow + nt * 8);
                int ci = wid * 64 + nt * 8 + tig * 2;
                float s0 = acc[mt][nt][hf * 2]     * 0.125f + ascf[ci]     + sh.x;
                float s1 = acc[mt][nt][hf * 2 + 1] * 0.125f + ascf[ci + 1] + sh.y;
                s0 = mk.x ? s0 : -1e9f;
                s1 = mk.y ? s1 : -1e9f;
                acc[mt][nt][hf * 2] = s0;
                acc[mt][nt][hf * 2 + 1] = s1;
                mx = fmaxf(mx, fmaxf(s0, s1));
            }
            mx = fmaxf(mx, __shfl_xor_sync(0xffffffffu, mx, 1));
            mx = fmaxf(mx, __shfl_xor_sync(0xffffffffu, mx, 2));
            if (tig == 0) redM[rl * 17 + wid] = mx;
        }
    }
    __syncthreads();
    if (tid < 32) {
        float m = redM[tid * 17];
#pragma unroll
        for (int w = 1; w < 16; w++) m = fmaxf(m, redM[tid * 17 + w]);
        redM2[tid] = m;
    }
    __syncthreads();

#pragma unroll
    for (int mt = 0; mt < 2; mt++) {
#pragma unroll
        for (int hf = 0; hf < 2; hf++) {
            int rl = mt * 16 + hf * 8 + q;
            float m = redM2[rl];
            float sum = 0.f;
#pragma unroll
            for (int nt = 0; nt < 8; nt++) {
                float e0 = __expf(acc[mt][nt][hf * 2] - m);
                float e1 = __expf(acc[mt][nt][hf * 2 + 1] - m);
                acc[mt][nt][hf * 2] = e0;
                acc[mt][nt][hf * 2 + 1] = e1;
                sum += e0 + e1;
            }
            sum += __shfl_xor_sync(0xffffffffu, sum, 1);
            sum += __shfl_xor_sync(0xffffffffu, sum, 2);
            if (tig == 0) redS[rl * 17 + wid] = sum;
        }
    }
    __syncthreads();
    if (tid < 32) {
        float s = 0.f;
#pragma unroll
        for (int w = 0; w < 16; w++) s += redS[tid * 17 + w];
        redS2[tid] = s;
    }
    __syncthreads();

#pragma unroll
    for (int mt = 0; mt < 2; mt++) {
#pragma unroll
        for (int hf = 0; hf < 2; hf++) {
            int rl = mt * 16 + hf * 8 + q;
            int grow = m0 + rl;
            float inv = 1.0f / redS2[rl];
            float* op = out + ((size_t)bh * S + grow) * S + wid * 64 + tig * 2;
#pragma unroll
            for (int nt = 0; nt < 8; nt++) {
                float2 o;
                o.x = acc[mt][nt][hf * 2] * inv;
                o.y = acc[mt][nt][hf * 2 + 1] * inv;
                *(float2*)(op + nt * 8) = o;
            }
        }
    }
}

// ---------------------------------------------------------------------------
extern "C" void kernel_launch(void* const* d_in, const int* in_sizes, int n_in,
                              void* d_out, int out_size)
{
    const float* query  = (const float*)d_in[0];
    const float* key    = (const float*)d_in[1];
    const int*   mask   = (const int*)  d_in[2];
    const float* aspect = (const float*)d_in[3];
    const float* shortp = (const float*)d_in[4];
    const float* Wq     = (const float*)d_in[5];
    const float* bq     = (const float*)d_in[6];
    const float* Wk     = (const float*)d_in[7];
    const float* bk     = (const float*)d_in[8];
    const float* Wd     = (const float*)d_in[9];
    const float* bd     = (const float*)d_in[10];
    const float* wm     = (const float*)d_in[11];
    const float* bm     = (const float*)d_in[12];
    float* out = (float*)d_out;

    cudaFuncSetAttribute(proj_kernel, cudaFuncAttributeMaxDynamicSharedMemorySize, 2 * PJ_BUF);
    cudaFuncSetAttribute(scores_kernel, cudaFuncAttributeMaxDynamicSharedMemorySize, SC_TOTAL);

    unsigned char* mask8;
    cudaGetSymbolAddress((void**)&mask8, g_mask8);

    const int nM4 = BATCH * S * S / 4;
    mask8_kernel<<<nM4 / 256, 256>>>(mask, mask8, nM4);

    // stage 1 of aspect is independent of proj -> launch first for overlap
    aspect1_kernel<<<BATCH * H, 256>>>(aspect, Wd, bd, wm);

    dim3 gp(32, 8, 2);                      // M tiles, N tiles, {Q,K}
    proj_kernel<<<gp, 256, 2 * PJ_BUF>>>(query, Wq, bq, key, Wk, bk);

    dim3 ga(S / 128, BATCH * H);
    aspect2_kernel<<<ga, 128>>>(bm);

    dim3 gs(S / 32, H, BATCH);
    scores_kernel<<<gs, 512, SC_TOTAL>>>(shortp, out);
}

// round 12
// speedup vs baseline: 1.0553x; 1.0278x over previous
#include <cuda_runtime.h>
#include <cuda_bf16.h>

#define BATCH 4
#define S 1024
#define D 1024
#define H 16
#define DK 64

// ---------------------------------------------------------------------------
// scratch (allocation-free: __device__ globals), split bf16: v ~= hi + lo
// ---------------------------------------------------------------------------
__device__ __nv_bfloat16 g_q_hi[BATCH * S * D];
__device__ __nv_bfloat16 g_q_lo[BATCH * S * D];
__device__ __nv_bfloat16 g_k_hi[BATCH * S * D];
__device__ __nv_bfloat16 g_k_lo[BATCH * S * D];
__device__ float g_asco[BATCH * H * S];
__device__ float g_aw[BATCH * H * DK];             // aspect @ Wd @ weight_m
__device__ unsigned char g_mask8[BATCH * S * S];   // packed mask bytes

// ---------------------------------------------------------------------------
// helpers
// ---------------------------------------------------------------------------
__device__ __forceinline__ unsigned sm_u32(const void* p) {
    return (unsigned)__cvta_generic_to_shared(p);
}

__device__ __forceinline__ void ldsm4(unsigned r[4], unsigned addr) {
    asm volatile("ldmatrix.sync.aligned.m8n8.x4.shared.b16 {%0,%1,%2,%3}, [%4];"
                 : "=r"(r[0]), "=r"(r[1]), "=r"(r[2]), "=r"(r[3])
                 : "r"(addr));
}

__device__ __forceinline__ void mma16816(float* c, const unsigned* a, const unsigned* b) {
    asm volatile(
        "mma.sync.aligned.m16n8k16.row.col.f32.bf16.bf16.f32 "
        "{%0,%1,%2,%3}, {%4,%5,%6,%7}, {%8,%9}, {%0,%1,%2,%3};"
        : "+f"(c[0]), "+f"(c[1]), "+f"(c[2]), "+f"(c[3])
        : "r"(a[0]), "r"(a[1]), "r"(a[2]), "r"(a[3]), "r"(b[0]), "r"(b[1]));
}

__device__ __forceinline__ void split_pack(float x, float y, unsigned& hi, unsigned& lo) {
    __nv_bfloat162 h, l;
    h.x = __float2bfloat16(x);
    h.y = __float2bfloat16(y);
    l.x = __float2bfloat16(x - __bfloat162float(h.x));
    l.y = __float2bfloat16(y - __bfloat162float(h.y));
    hi = *reinterpret_cast<unsigned*>(&h);
    lo = *reinterpret_cast<unsigned*>(&l);
}

__device__ __forceinline__ void cpa16(unsigned dst, const void* src) {
    asm volatile("cp.async.cg.shared.global [%0], [%1], 16;" :: "r"(dst), "l"(src));
}
#define CP_COMMIT() asm volatile("cp.async.commit_group;")
#define CP_WAIT(N)  asm volatile("cp.async.wait_group %0;" :: "n"(N))

// ---------------------------------------------------------------------------
// Kernel 0: pack mask int32 {0,1} -> uint8 (exact).
// ---------------------------------------------------------------------------
__global__ __launch_bounds__(256) void mask8_kernel(
    const int* __restrict__ m, unsigned char* __restrict__ o, int n4)
{
    int i = blockIdx.x * 256 + threadIdx.x;
    if (i < n4) {
        int4 v = ((const int4*)m)[i];
        uchar4 u;
        u.x = (unsigned char)v.x; u.y = (unsigned char)v.y;
        u.z = (unsigned char)v.z; u.w = (unsigned char)v.w;
        ((uchar4*)o)[i] = u;
    }
}

// ---------------------------------------------------------------------------
// Kernel 1 (round-3 proven, 183us): C = X @ W^T + bias, z in {Q, K}.
// 128x128 CTA tile, BK=32, double-buffered smem, inline fp32->hi/lo convert,
// 3-term split-bf16 mma, 8 warps, warp tile 32x64.
// ---------------------------------------------------------------------------
#define PJ_AHI 0
#define PJ_ALO 10240
#define PJ_BHI 20480
#define PJ_BLO 30720
#define PJ_BUF 40960

__global__ void __launch_bounds__(256, 1) proj_kernel(
    const float* __restrict__ Xq, const float* __restrict__ Wq, const float* __restrict__ bq,
    const float* __restrict__ Xk, const float* __restrict__ Wk, const float* __restrict__ bk)
{
    extern __shared__ char smem_raw[];
    const bool is_k = blockIdx.z != 0;
    const float* __restrict__ X = is_k ? Xk : Xq;
    const float* __restrict__ W = is_k ? Wk : Wq;
    const float* __restrict__ bias = is_k ? bk : bq;
    __nv_bfloat16* __restrict__ Chi = is_k ? g_k_hi : g_q_hi;
    __nv_bfloat16* __restrict__ Clo = is_k ? g_k_lo : g_q_lo;

    const int tid = threadIdx.x;
    const int lane = tid & 31;
    const int wid = tid >> 5;
    const int wm = wid & 3;
    const int wn = wid >> 2;
    const int m0 = blockIdx.x * 128;
    const int n0 = blockIdx.y * 128;
    const unsigned sbase = sm_u32(smem_raw);

    float acc[2][8][4];
#pragma unroll
    for (int mt = 0; mt < 2; mt++)
#pragma unroll
        for (int nt = 0; nt < 8; nt++)
#pragma unroll
            for (int i = 0; i < 4; i++) acc[mt][nt][i] = 0.f;

    float4 ra[4], rb[4];

#pragma unroll
    for (int l = 0; l < 4; l++) {
        int f = tid + l * 256;
        int row = f >> 3, c4 = f & 7;
        ra[l] = *(const float4*)(X + (size_t)(m0 + row) * D + c4 * 4);
        rb[l] = *(const float4*)(W + (size_t)(n0 + row) * D + c4 * 4);
    }
#pragma unroll
    for (int l = 0; l < 4; l++) {
        int f = tid + l * 256;
        int row = f >> 3, c4 = f & 7;
        unsigned h0, l0, h1, l1;
        split_pack(ra[l].x, ra[l].y, h0, l0);
        split_pack(ra[l].z, ra[l].w, h1, l1);
        *(uint2*)(smem_raw + PJ_AHI + row * 80 + c4 * 8) = make_uint2(h0, h1);
        *(uint2*)(smem_raw + PJ_ALO + row * 80 + c4 * 8) = make_uint2(l0, l1);
        split_pack(rb[l].x, rb[l].y, h0, l0);
        split_pack(rb[l].z, rb[l].w, h1, l1);
        *(uint2*)(smem_raw + PJ_BHI + row * 80 + c4 * 8) = make_uint2(h0, h1);
        *(uint2*)(smem_raw + PJ_BLO + row * 80 + c4 * 8) = make_uint2(l0, l1);
    }
    __syncthreads();

    for (int c = 0; c < 32; c++) {
        if (c < 31) {
            int k0 = (c + 1) * 32;
#pragma unroll
            for (int l = 0; l < 4; l++) {
                int f = tid + l * 256;
                int row = f >> 3, c4 = f & 7;
                ra[l] = *(const float4*)(X + (size_t)(m0 + row) * D + k0 + c4 * 4);
                rb[l] = *(const float4*)(W + (size_t)(n0 + row) * D + k0 + c4 * 4);
            }
        }
        {
            const unsigned base = sbase + (c & 1) * PJ_BUF;
#pragma unroll
            for (int kk = 0; kk < 2; kk++) {
                unsigned ahi[2][4], alo[2][4];
#pragma unroll
                for (int mt = 0; mt < 2; mt++) {
                    unsigned rbytes = (unsigned)(wm * 32 + mt * 16 + (lane & 7) + ((lane >> 3) & 1) * 8) * 80
                                    + ((lane >> 4) & 1) * 16 + kk * 32;
                    ldsm4(ahi[mt], base + PJ_AHI + rbytes);
                    ldsm4(alo[mt], base + PJ_ALO + rbytes);
                }
#pragma unroll
                for (int nt2 = 0; nt2 < 4; nt2++) {
                    unsigned rbytes = (unsigned)(wn * 64 + nt2 * 16 + (lane & 7) + ((lane >> 4) & 1) * 8) * 80
                                    + ((lane >> 3) & 1) * 16 + kk * 32;
                    unsigned bhi[4], blo[4];
                    ldsm4(bhi, base + PJ_BHI + rbytes);
                    ldsm4(blo, base + PJ_BLO + rbytes);
#pragma unroll
                    for (int mt = 0; mt < 2; mt++) {
                        mma16816(acc[mt][nt2 * 2],     ahi[mt], bhi);
                        mma16816(acc[mt][nt2 * 2 + 1], ahi[mt], bhi + 2);
                        mma16816(acc[mt][nt2 * 2],     ahi[mt], blo);
                        mma16816(acc[mt][nt2 * 2 + 1], ahi[mt], blo + 2);
                        mma16816(acc[mt][nt2 * 2],     alo[mt], bhi);
                        mma16816(acc[mt][nt2 * 2 + 1], alo[mt], bhi + 2);
                    }
                }
            }
        }
        if (c < 31) {
            char* dst = smem_raw + ((c + 1) & 1) * PJ_BUF;
#pragma unroll
            for (int l = 0; l < 4; l++) {
                int f = tid + l * 256;
                int row = f >> 3, c4 = f & 7;
                unsigned h0, l0, h1, l1;
                split_pack(ra[l].x, ra[l].y, h0, l0);
                split_pack(ra[l].z, ra[l].w, h1, l1);
                *(uint2*)(dst + PJ_AHI + row * 80 + c4 * 8) = make_uint2(h0, h1);
                *(uint2*)(dst + PJ_ALO + row * 80 + c4 * 8) = make_uint2(l0, l1);
                split_pack(rb[l].x, rb[l].y, h0, l0);
                split_pack(rb[l].z, rb[l].w, h1, l1);
                *(uint2*)(dst + PJ_BHI + row * 80 + c4 * 8) = make_uint2(h0, h1);
                *(uint2*)(dst + PJ_BLO + row * 80 + c4 * 8) = make_uint2(l0, l1);
            }
            __syncthreads();
        }
    }

    const int q = lane >> 2, tig = lane & 3;
#pragma unroll
    for (int mt = 0; mt < 2; mt++) {
#pragma unroll
        for (int nt = 0; nt < 8; nt++) {
            int col = n0 + wn * 64 + nt * 8 + tig * 2;
            float2 bb = *(const float2*)(bias + col);
            int row = m0 + wm * 32 + mt * 16 + q;
            unsigned hi, lo;
            split_pack(acc[mt][nt][0] + bb.x, acc[mt][nt][1] + bb.y, hi, lo);
            *reinterpret_cast<unsigned*>(&Chi[(size_t)row * D + col]) = hi;
            *reinterpret_cast<unsigned*>(&Clo[(size_t)row * D + col]) = lo;
            split_pack(acc[mt][nt][2] + bb.x, acc[mt][nt][3] + bb.y, hi, lo);
            *reinterpret_cast<unsigned*>(&Chi[(size_t)(row + 8) * D + col]) = hi;
            *reinterpret_cast<unsigned*>(&Clo[(size_t)(row + 8) * D + col]) = lo;
        }
    }
}

// ---------------------------------------------------------------------------
// Kernel 2a: aspect stage 1 — aw[b,h,:] = (aspect[b] @ Wd^T + bd) @ wm[h].
// ---------------------------------------------------------------------------
__global__ __launch_bounds__(256) void aspect1_kernel(
    const float* __restrict__ aspect, const float* __restrict__ Wd, const float* __restrict__ bd,
    const float* __restrict__ wm)
{
    const int bh = blockIdx.x;
    const int b = bh >> 4;
    const int h = bh & 15;
    const int tid = threadIdx.x;

    __shared__ float asp_s[64];

    {
        int e = tid >> 2, p = tid & 3;
        const float* av = aspect + (size_t)b * D + p * 256;
        const float* wv = Wd + (size_t)e * D + p * 256;
        float sum = 0.f;
#pragma unroll 4
        for (int d = 0; d < 256; d += 4) {
            float4 a = *(const float4*)(av + d);
            float4 w = *(const float4*)(wv + d);
            sum += a.x * w.x + a.y * w.y + a.z * w.z + a.w * w.w;
        }
        sum += __shfl_xor_sync(0xffffffffu, sum, 1, 4);
        sum += __shfl_xor_sync(0xffffffffu, sum, 2, 4);
        if (p == 0) asp_s[e] = sum + bd[e];
    }
    __syncthreads();
    if (tid < 64) {
        float s = 0.f;
        const float* w = wm + (size_t)h * DK * DK + tid;
#pragma unroll 8
        for (int c = 0; c < 64; c++) s += asp_s[c] * w[c * 64];
        g_aw[bh * DK + tid] = s;
    }
}

// ---------------------------------------------------------------------------
// Kernel 2b: aspect stage 2 — asco[b,h,j] = tanh(aw[b,h] . k[b,h,j] + bias_m).
// COALESCED: 8 threads per row (tid = r*8+g, g-th 16B granule of hi and lo),
// shfl reduce within 8-lane groups. grid (S/16, B*H) x 128 threads.
// ---------------------------------------------------------------------------
__global__ __launch_bounds__(128) void aspect2_kernel(const float* __restrict__ bm)
{
    const int bh = blockIdx.y;
    const int b = bh >> 4;
    const int h = bh & 15;
    const int tid = threadIdx.x;
    const int r = tid >> 3;               // 0..15: row within CTA tile
    const int g = tid & 7;                // 0..7: 16B granule within row
    const int j = blockIdx.x * 16 + r;

    __shared__ float aw_s[64];
    if (tid < 64) aw_s[tid] = g_aw[bh * DK + tid];
    __syncthreads();

    const size_t rowoff = ((size_t)b * S + j) * D + h * DK;
    uint4 vh = *(const uint4*)(g_k_hi + rowoff + g * 8);
    uint4 vl = *(const uint4*)(g_k_lo + rowoff + g * 8);

    const __nv_bfloat162* ph = reinterpret_cast<const __nv_bfloat162*>(&vh);
    const __nv_bfloat162* pl = reinterpret_cast<const __nv_bfloat162*>(&vl);
    float s = 0.f;
#pragma unroll
    for (int i = 0; i < 4; i++) {
        float2 a = __bfloat1622float2(ph[i]);
        float2 c = __bfloat1622float2(pl[i]);
        s += aw_s[g * 8 + 2 * i] * (a.x + c.x) + aw_s[g * 8 + 2 * i + 1] * (a.y + c.y);
    }
    // reduce over the 8 granule-threads of this row
    s += __shfl_xor_sync(0xffffffffu, s, 1, 8);
    s += __shfl_xor_sync(0xffffffffu, s, 2, 8);
    s += __shfl_xor_sync(0xffffffffu, s, 4, 8);

    if (g == 0) {
        float x = s + bm[0];
        float t = 1.f - 2.f / (__expf(2.f * x) + 1.f);
        g_asco[(size_t)bh * S + j] = t;
    }
}

// ---------------------------------------------------------------------------
// Kernel 3 (measured 268.9us): fused scores + softmax, v1 structure
// + packed-mask cp.async staging.
// ---------------------------------------------------------------------------
#define SC_SQHI 0
#define SC_SQLO 4608
#define SC_ASCS 9216
#define SC_REDM 13312
#define SC_REDS 15488
#define SC_REDM2 17664
#define SC_REDS2 17792
#define SC_SKHI 17920
#define SC_SKLO 99840
#define SC_MASK 181760
#define SC_TOTAL (SC_MASK + 32 * 1040)   // 215040

__global__ void __launch_bounds__(512, 1) scores_kernel(
    const float* __restrict__ shortp, float* __restrict__ out)
{
    extern __shared__ char smem_raw[];
    const int b = blockIdx.z;
    const int h = blockIdx.y;
    const int m0 = blockIdx.x * 32;
    const int bh = b * H + h;
    const int tid = threadIdx.x;
    const int lane = tid & 31;
    const int wid = tid >> 5;
    const unsigned sbase = sm_u32(smem_raw);

    // ---- stage mask bytes (32 rows x 1024) via cp.async; lands during mma ----
#pragma unroll
    for (int l = 0; l < 4; l++) {
        int f = tid + l * 512;
        int row = f >> 6, g = f & 63;
        cpa16(sbase + SC_MASK + row * 1040 + g * 16,
              g_mask8 + ((size_t)(b * S) + m0 + row) * S + g * 16);
    }
    CP_COMMIT();

    {
        int row = tid >> 4, g = tid & 15;
        size_t goff = ((size_t)(b * S) + m0 + row) * D + h * DK + g * 4;
        *(uint2*)(smem_raw + SC_SQHI + row * 144 + g * 8) = *(const uint2*)(g_q_hi + goff);
        *(uint2*)(smem_raw + SC_SQLO + row * 144 + g * 8) = *(const uint2*)(g_q_lo + goff);
    }
    ((float2*)(smem_raw + SC_ASCS))[tid] = *(const float2*)(g_asco + (size_t)bh * S + tid * 2);

    float acc[2][8][4];
#pragma unroll
    for (int mt = 0; mt < 2; mt++)
#pragma unroll
        for (int nt = 0; nt < 8; nt++)
#pragma unroll
            for (int i = 0; i < 4; i++) acc[mt][nt][i] = 0.f;

    for (int chunk = 0; chunk < 2; chunk++) {
        if (chunk) __syncthreads();
#pragma unroll
        for (int l = 0; l < 8; l++) {
            int f = tid + l * 512;
            int row = f >> 2, g = f & 3;
            size_t goff = ((size_t)(b * S) + row) * D + h * DK + chunk * 32 + g * 8;
            *(uint4*)(smem_raw + SC_SKHI + row * 80 + g * 16) = *(const uint4*)(g_k_hi + goff);
            *(uint4*)(smem_raw + SC_SKLO + row * 80 + g * 16) = *(const uint4*)(g_k_lo + goff);
        }
        __syncthreads();

#pragma unroll
        for (int kk2 = 0; kk2 < 2; kk2++) {
            const int kglob = chunk * 2 + kk2;
            unsigned ahi[2][4], alo[2][4];
#pragma unroll
            for (int mt = 0; mt < 2; mt++) {
                unsigned rbytes = (unsigned)(mt * 16 + (lane & 7) + ((lane >> 3) & 1) * 8) * 144
                                + ((lane >> 4) & 1) * 16 + kglob * 32;
                ldsm4(ahi[mt], sbase + SC_SQHI + rbytes);
                ldsm4(alo[mt], sbase + SC_SQLO + rbytes);
            }
#pragma unroll
            for (int nt2 = 0; nt2 < 4; nt2++) {
                unsigned rbytes = (unsigned)(wid * 64 + nt2 * 16 + (lane & 7) + ((lane >> 4) & 1) * 8) * 80
                                + ((lane >> 3) & 1) * 16 + kk2 * 32;
                unsigned bhi[4], blo[4];
                ldsm4(bhi, sbase + SC_SKHI + rbytes);
                ldsm4(blo, sbase + SC_SKLO + rbytes);
#pragma unroll
                for (int mt = 0; mt < 2; mt++) {
                    mma16816(acc[mt][nt2 * 2],     ahi[mt], bhi);
                    mma16816(acc[mt][nt2 * 2 + 1], ahi[mt], bhi + 2);
                    mma16816(acc[mt][nt2 * 2],     ahi[mt], blo);
                    mma16816(acc[mt][nt2 * 2 + 1], ahi[mt], blo + 2);
                    mma16816(acc[mt][nt2 * 2],     alo[mt], bhi);
                    mma16816(acc[mt][nt2 * 2 + 1], alo[mt], bhi + 2);
                }
            }
        }
    }

    CP_WAIT(0);
    __syncthreads();

    // ---- fused epilogue: /8 + asco + short, mask (smem bytes), softmax ----
    const int q = lane >> 2, tig = lane & 3;
    const float* ascf = (const float*)(smem_raw + SC_ASCS);
    float* redM = (float*)(smem_raw + SC_REDM);
    float* redS = (float*)(smem_raw + SC_REDS);
    float* redM2 = (float*)(smem_raw + SC_REDM2);
    float* redS2 = (float*)(smem_raw + SC_REDS2);

#pragma unroll
    for (int mt = 0; mt < 2; mt++) {
#pragma unroll
        for (int hf = 0; hf < 2; hf++) {
            int rl = mt * 16 + hf * 8 + q;
            int grow = m0 + rl;
            const float* shp = shortp + ((size_t)bh * S + grow) * S + wid * 64 + tig * 2;
            const unsigned char* mrow =
                (const unsigned char*)(smem_raw + SC_MASK + rl * 1040 + wid * 64 + tig * 2);
            float mx = -1e30f;
#pragma unroll
            for (int nt = 0; nt < 8; nt++) {
                float2 sh = *(const float2*)(shp + nt * 8);
                uchar2 mk = *(const uchar2*)(mrow + nt * 8);
                int ci = wid * 64 + nt * 8 + tig * 2;
                float s0 = acc[mt][nt][hf * 2]     * 0.125f + ascf[ci]     + sh.x;
                float s1 = acc[mt][nt][hf * 2 + 1] * 0.125f + ascf[ci + 1] + sh.y;
                s0 = mk.x ? s0 : -1e9f;
                s1 = mk.y ? s1 : -1e9f;
                acc[mt][nt][hf * 2] = s0;
                acc[mt][nt][hf * 2 + 1] = s1;
                mx = fmaxf(mx, fmaxf(s0, s1));
            }
            mx = fmaxf(mx, __shfl_xor_sync(0xffffffffu, mx, 1));
            mx = fmaxf(mx, __shfl_xor_sync(0xffffffffu, mx, 2));
            if (tig == 0) redM[rl * 17 + wid] = mx;
        }
    }
    __syncthreads();
    if (tid < 32) {
        float m = redM[tid * 17];
#pragma unroll
        for (int w = 1; w < 16; w++) m = fmaxf(m, redM[tid * 17 + w]);
        redM2[tid] = m;
    }
    __syncthreads();

#pragma unroll
    for (int mt = 0; mt < 2; mt++) {
#pragma unroll
        for (int hf = 0; hf < 2; hf++) {
            int rl = mt * 16 + hf * 8 + q;
            float m = redM2[rl];
            float sum = 0.f;
#pragma unroll
            for (int nt = 0; nt < 8; nt++) {
                float e0 = __expf(acc[mt][nt][hf * 2] - m);
                float e1 = __expf(acc[mt][nt][hf * 2 + 1] - m);
                acc[mt][nt][hf * 2] = e0;
                acc[mt][nt][hf * 2 + 1] = e1;
                sum += e0 + e1;
            }
            sum += __shfl_xor_sync(0xffffffffu, sum, 1);
            sum += __shfl_xor_sync(0xffffffffu, sum, 2);
            if (tig == 0) redS[rl * 17 + wid] = sum;
        }
    }
    __syncthreads();
    if (tid < 32) {
        float s = 0.f;
#pragma unroll
        for (int w = 0; w < 16; w++) s += redS[tid * 17 + w];
        redS2[tid] = s;
    }
    __syncthreads();

#pragma unroll
    for (int mt = 0; mt < 2; mt++) {
#pragma unroll
        for (int hf = 0; hf < 2; hf++) {
            int rl = mt * 16 + hf * 8 + q;
            int grow = m0 + rl;
            float inv = 1.0f / redS2[rl];
            float* op = out + ((size_t)bh * S + grow) * S + wid * 64 + tig * 2;
#pragma unroll
            for (int nt = 0; nt < 8; nt++) {
                float2 o;
                o.x = acc[mt][nt][hf * 2] * inv;
                o.y = acc[mt][nt][hf * 2 + 1] * inv;
                *(float2*)(op + nt * 8) = o;
            }
        }
    }
}

// ---------------------------------------------------------------------------
extern "C" void kernel_launch(void* const* d_in, const int* in_sizes, int n_in,
                              void* d_out, int out_size)
{
    const float* query  = (const float*)d_in[0];
    const float* key    = (const float*)d_in[1];
    const int*   mask   = (const int*)  d_in[2];
    const float* aspect = (const float*)d_in[3];
    const float* shortp = (const float*)d_in[4];
    const float* Wq     = (const float*)d_in[5];
    const float* bq     = (const float*)d_in[6];
    const float* Wk     = (const float*)d_in[7];
    const float* bk     = (const float*)d_in[8];
    const float* Wd     = (const float*)d_in[9];
    const float* bd     = (const float*)d_in[10];
    const float* wm     = (const float*)d_in[11];
    const float* bm     = (const float*)d_in[12];
    float* out = (float*)d_out;

    cudaFuncSetAttribute(proj_kernel, cudaFuncAttributeMaxDynamicSharedMemorySize, 2 * PJ_BUF);
    cudaFuncSetAttribute(scores_kernel, cudaFuncAttributeMaxDynamicSharedMemorySize, SC_TOTAL);

    unsigned char* mask8;
    cudaGetSymbolAddress((void**)&mask8, g_mask8);

    const int nM4 = BATCH * S * S / 4;
    mask8_kernel<<<nM4 / 256, 256>>>(mask, mask8, nM4);

    // stage 1 of aspect is independent of proj -> launch first for overlap
    aspect1_kernel<<<BATCH * H, 256>>>(aspect, Wd, bd, wm);

    dim3 gp(32, 8, 2);                      // M tiles, N tiles, {Q,K}
    proj_kernel<<<gp, 256, 2 * PJ_BUF>>>(query, Wq, bq, key, Wk, bk);

    dim3 ga(S / 16, BATCH * H);
    aspect2_kernel<<<ga, 128>>>(bm);

    dim3 gs(S / 32, H, BATCH);
    scores_kernel<<<gs, 512, SC_TOTAL>>>(shortp, out);
}

// round 13
// speedup vs baseline: 1.0693x; 1.0132x over previous
#include <cuda_runtime.h>
#include <cuda_bf16.h>

#define BATCH 4
#define S 1024
#define D 1024
#define H 16
#define DK 64

// ---------------------------------------------------------------------------
// scratch (allocation-free: __device__ globals), split bf16: v ~= hi + lo
// ---------------------------------------------------------------------------
__device__ __nv_bfloat16 g_q_hi[BATCH * S * D];
__device__ __nv_bfloat16 g_q_lo[BATCH * S * D];
__device__ __nv_bfloat16 g_k_hi[BATCH * S * D];
__device__ __nv_bfloat16 g_k_lo[BATCH * S * D];
__device__ float g_asco[BATCH * H * S];
__device__ float g_aw[BATCH * H * DK];             // aspect @ Wd @ weight_m
__device__ unsigned char g_mask8[BATCH * S * S];   // packed mask bytes

// ---------------------------------------------------------------------------
// helpers
// ---------------------------------------------------------------------------
__device__ __forceinline__ unsigned sm_u32(const void* p) {
    return (unsigned)__cvta_generic_to_shared(p);
}

__device__ __forceinline__ void ldsm4(unsigned r[4], unsigned addr) {
    asm volatile("ldmatrix.sync.aligned.m8n8.x4.shared.b16 {%0,%1,%2,%3}, [%4];"
                 : "=r"(r[0]), "=r"(r[1]), "=r"(r[2]), "=r"(r[3])
                 : "r"(addr));
}

__device__ __forceinline__ void mma16816(float* c, const unsigned* a, const unsigned* b) {
    asm volatile(
        "mma.sync.aligned.m16n8k16.row.col.f32.bf16.bf16.f32 "
        "{%0,%1,%2,%3}, {%4,%5,%6,%7}, {%8,%9}, {%0,%1,%2,%3};"
        : "+f"(c[0]), "+f"(c[1]), "+f"(c[2]), "+f"(c[3])
        : "r"(a[0]), "r"(a[1]), "r"(a[2]), "r"(a[3]), "r"(b[0]), "r"(b[1]));
}

__device__ __forceinline__ void split_pack(float x, float y, unsigned& hi, unsigned& lo) {
    __nv_bfloat162 h, l;
    h.x = __float2bfloat16(x);
    h.y = __float2bfloat16(y);
    l.x = __float2bfloat16(x - __bfloat162float(h.x));
    l.y = __float2bfloat16(y - __bfloat162float(h.y));
    hi = *reinterpret_cast<unsigned*>(&h);
    lo = *reinterpret_cast<unsigned*>(&l);
}

__device__ __forceinline__ void cpa16(unsigned dst, const void* src) {
    asm volatile("cp.async.cg.shared.global [%0], [%1], 16;" :: "r"(dst), "l"(src));
}
#define CP_COMMIT() asm volatile("cp.async.commit_group;")
#define CP_WAIT(N)  asm volatile("cp.async.wait_group %0;" :: "n"(N))

// ---------------------------------------------------------------------------
// Kernel 0: pack mask int32 {0,1} -> uint8 (exact).
// ---------------------------------------------------------------------------
__global__ __launch_bounds__(256) void mask8_kernel(
    const int* __restrict__ m, unsigned char* __restrict__ o, int n4)
{
    int i = blockIdx.x * 256 + threadIdx.x;
    if (i < n4) {
        int4 v = ((const int4*)m)[i];
        uchar4 u;
        u.x = (unsigned char)v.x; u.y = (unsigned char)v.y;
        u.z = (unsigned char)v.z; u.w = (unsigned char)v.w;
        ((uchar4*)o)[i] = u;
    }
}

// ---------------------------------------------------------------------------
// Kernel 1 (round-3 proven, 183us): C = X @ W^T + bias, z in {Q, K}.
// ---------------------------------------------------------------------------
#define PJ_AHI 0
#define PJ_ALO 10240
#define PJ_BHI 20480
#define PJ_BLO 30720
#define PJ_BUF 40960

__global__ void __launch_bounds__(256, 1) proj_kernel(
    const float* __restrict__ Xq, const float* __restrict__ Wq, const float* __restrict__ bq,
    const float* __restrict__ Xk, const float* __restrict__ Wk, const float* __restrict__ bk)
{
    extern __shared__ char smem_raw[];
    const bool is_k = blockIdx.z != 0;
    const float* __restrict__ X = is_k ? Xk : Xq;
    const float* __restrict__ W = is_k ? Wk : Wq;
    const float* __restrict__ bias = is_k ? bk : bq;
    __nv_bfloat16* __restrict__ Chi = is_k ? g_k_hi : g_q_hi;
    __nv_bfloat16* __restrict__ Clo = is_k ? g_k_lo : g_q_lo;

    const int tid = threadIdx.x;
    const int lane = tid & 31;
    const int wid = tid >> 5;
    const int wm = wid & 3;
    const int wn = wid >> 2;
    const int m0 = blockIdx.x * 128;
    const int n0 = blockIdx.y * 128;
    const unsigned sbase = sm_u32(smem_raw);

    float acc[2][8][4];
#pragma unroll
    for (int mt = 0; mt < 2; mt++)
#pragma unroll
        for (int nt = 0; nt < 8; nt++)
#pragma unroll
            for (int i = 0; i < 4; i++) acc[mt][nt][i] = 0.f;

    float4 ra[4], rb[4];

#pragma unroll
    for (int l = 0; l < 4; l++) {
        int f = tid + l * 256;
        int row = f >> 3, c4 = f & 7;
        ra[l] = *(const float4*)(X + (size_t)(m0 + row) * D + c4 * 4);
        rb[l] = *(const float4*)(W + (size_t)(n0 + row) * D + c4 * 4);
    }
#pragma unroll
    for (int l = 0; l < 4; l++) {
        int f = tid + l * 256;
        int row = f >> 3, c4 = f & 7;
        unsigned h0, l0, h1, l1;
        split_pack(ra[l].x, ra[l].y, h0, l0);
        split_pack(ra[l].z, ra[l].w, h1, l1);
        *(uint2*)(smem_raw + PJ_AHI + row * 80 + c4 * 8) = make_uint2(h0, h1);
        *(uint2*)(smem_raw + PJ_ALO + row * 80 + c4 * 8) = make_uint2(l0, l1);
        split_pack(rb[l].x, rb[l].y, h0, l0);
        split_pack(rb[l].z, rb[l].w, h1, l1);
        *(uint2*)(smem_raw + PJ_BHI + row * 80 + c4 * 8) = make_uint2(h0, h1);
        *(uint2*)(smem_raw + PJ_BLO + row * 80 + c4 * 8) = make_uint2(l0, l1);
    }
    __syncthreads();

    for (int c = 0; c < 32; c++) {
        if (c < 31) {
            int k0 = (c + 1) * 32;
#pragma unroll
            for (int l = 0; l < 4; l++) {
                int f = tid + l * 256;
                int row = f >> 3, c4 = f & 7;
                ra[l] = *(const float4*)(X + (size_t)(m0 + row) * D + k0 + c4 * 4);
                rb[l] = *(const float4*)(W + (size_t)(n0 + row) * D + k0 + c4 * 4);
            }
        }
        {
            const unsigned base = sbase + (c & 1) * PJ_BUF;
#pragma unroll
            for (int kk = 0; kk < 2; kk++) {
                unsigned ahi[2][4], alo[2][4];
#pragma unroll
                for (int mt = 0; mt < 2; mt++) {
                    unsigned rbytes = (unsigned)(wm * 32 + mt * 16 + (lane & 7) + ((lane >> 3) & 1) * 8) * 80
                                    + ((lane >> 4) & 1) * 16 + kk * 32;
                    ldsm4(ahi[mt], base + PJ_AHI + rbytes);
                    ldsm4(alo[mt], base + PJ_ALO + rbytes);
                }
#pragma unroll
                for (int nt2 = 0; nt2 < 4; nt2++) {
                    unsigned rbytes = (unsigned)(wn * 64 + nt2 * 16 + (lane & 7) + ((lane >> 4) & 1) * 8) * 80
                                    + ((lane >> 3) & 1) * 16 + kk * 32;
                    unsigned bhi[4], blo[4];
                    ldsm4(bhi, base + PJ_BHI + rbytes);
                    ldsm4(blo, base + PJ_BLO + rbytes);
#pragma unroll
                    for (int mt = 0; mt < 2; mt++) {
                        mma16816(acc[mt][nt2 * 2],     ahi[mt], bhi);
                        mma16816(acc[mt][nt2 * 2 + 1], ahi[mt], bhi + 2);
                        mma16816(acc[mt][nt2 * 2],     ahi[mt], blo);
                        mma16816(acc[mt][nt2 * 2 + 1], ahi[mt], blo + 2);
                        mma16816(acc[mt][nt2 * 2],     alo[mt], bhi);
                        mma16816(acc[mt][nt2 * 2 + 1], alo[mt], bhi + 2);
                    }
                }
            }
        }
        if (c < 31) {
            char* dst = smem_raw + ((c + 1) & 1) * PJ_BUF;
#pragma unroll
            for (int l = 0; l < 4; l++) {
                int f = tid + l * 256;
                int row = f >> 3, c4 = f & 7;
                unsigned h0, l0, h1, l1;
                split_pack(ra[l].x, ra[l].y, h0, l0);
                split_pack(ra[l].z, ra[l].w, h1, l1);
                *(uint2*)(dst + PJ_AHI + row * 80 + c4 * 8) = make_uint2(h0, h1);
                *(uint2*)(dst + PJ_ALO + row * 80 + c4 * 8) = make_uint2(l0, l1);
                split_pack(rb[l].x, rb[l].y, h0, l0);
                split_pack(rb[l].z, rb[l].w, h1, l1);
                *(uint2*)(dst + PJ_BHI + row * 80 + c4 * 8) = make_uint2(h0, h1);
                *(uint2*)(dst + PJ_BLO + row * 80 + c4 * 8) = make_uint2(l0, l1);
            }
            __syncthreads();
        }
    }

    const int q = lane >> 2, tig = lane & 3;
#pragma unroll
    for (int mt = 0; mt < 2; mt++) {
#pragma unroll
        for (int nt = 0; nt < 8; nt++) {
            int col = n0 + wn * 64 + nt * 8 + tig * 2;
            float2 bb = *(const float2*)(bias + col);
            int row = m0 + wm * 32 + mt * 16 + q;
            unsigned hi, lo;
            split_pack(acc[mt][nt][0] + bb.x, acc[mt][nt][1] + bb.y, hi, lo);
            *reinterpret_cast<unsigned*>(&Chi[(size_t)row * D + col]) = hi;
            *reinterpret_cast<unsigned*>(&Clo[(size_t)row * D + col]) = lo;
            split_pack(acc[mt][nt][2] + bb.x, acc[mt][nt][3] + bb.y, hi, lo);
            *reinterpret_cast<unsigned*>(&Chi[(size_t)(row + 8) * D + col]) = hi;
            *reinterpret_cast<unsigned*>(&Clo[(size_t)(row + 8) * D + col]) = lo;
        }
    }
}

// ---------------------------------------------------------------------------
// Kernel 2a: aspect stage 1 — aw[b,h,:] = (aspect[b] @ Wd^T + bd) @ wm[h].
// ---------------------------------------------------------------------------
__global__ __launch_bounds__(256) void aspect1_kernel(
    const float* __restrict__ aspect, const float* __restrict__ Wd, const float* __restrict__ bd,
    const float* __restrict__ wm)
{
    const int bh = blockIdx.x;
    const int b = bh >> 4;
    const int h = bh & 15;
    const int tid = threadIdx.x;

    __shared__ float asp_s[64];

    {
        int e = tid >> 2, p = tid & 3;
        const float* av = aspect + (size_t)b * D + p * 256;
        const float* wv = Wd + (size_t)e * D + p * 256;
        float sum = 0.f;
#pragma unroll 4
        for (int d = 0; d < 256; d += 4) {
            float4 a = *(const float4*)(av + d);
            float4 w = *(const float4*)(wv + d);
            sum += a.x * w.x + a.y * w.y + a.z * w.z + a.w * w.w;
        }
        sum += __shfl_xor_sync(0xffffffffu, sum, 1, 4);
        sum += __shfl_xor_sync(0xffffffffu, sum, 2, 4);
        if (p == 0) asp_s[e] = sum + bd[e];
    }
    __syncthreads();
    if (tid < 64) {
        float s = 0.f;
        const float* w = wm + (size_t)h * DK * DK + tid;
#pragma unroll 8
        for (int c = 0; c < 64; c++) s += asp_s[c] * w[c * 64];
        g_aw[bh * DK + tid] = s;
    }
}

// ---------------------------------------------------------------------------
// Kernel 2b: aspect stage 2 (coalesced, measured 8.4us).
// ---------------------------------------------------------------------------
__global__ __launch_bounds__(128) void aspect2_kernel(const float* __restrict__ bm)
{
    const int bh = blockIdx.y;
    const int b = bh >> 4;
    const int h = bh & 15;
    const int tid = threadIdx.x;
    const int r = tid >> 3;
    const int g = tid & 7;
    const int j = blockIdx.x * 16 + r;

    __shared__ float aw_s[64];
    if (tid < 64) aw_s[tid] = g_aw[bh * DK + tid];
    __syncthreads();

    const size_t rowoff = ((size_t)b * S + j) * D + h * DK;
    uint4 vh = *(const uint4*)(g_k_hi + rowoff + g * 8);
    uint4 vl = *(const uint4*)(g_k_lo + rowoff + g * 8);

    const __nv_bfloat162* ph = reinterpret_cast<const __nv_bfloat162*>(&vh);
    const __nv_bfloat162* pl = reinterpret_cast<const __nv_bfloat162*>(&vl);
    float s = 0.f;
#pragma unroll
    for (int i = 0; i < 4; i++) {
        float2 a = __bfloat1622float2(ph[i]);
        float2 c = __bfloat1622float2(pl[i]);
        s += aw_s[g * 8 + 2 * i] * (a.x + c.x) + aw_s[g * 8 + 2 * i + 1] * (a.y + c.y);
    }
    s += __shfl_xor_sync(0xffffffffu, s, 1, 8);
    s += __shfl_xor_sync(0xffffffffu, s, 2, 8);
    s += __shfl_xor_sync(0xffffffffu, s, 4, 8);

    if (g == 0) {
        float x = s + bm[0];
        float t = 1.f - 2.f / (__expf(2.f * x) + 1.f);
        g_asco[(size_t)bh * S + j] = t;
    }
}

// ---------------------------------------------------------------------------
// Kernel 3 v3: fused scores + softmax.
// Changes vs measured 270us version:
//  - K smem uses XOR swizzle at 64B row stride (saves 32KB, same ldsm pattern)
//  - 8 rows of `short` (32KB) staged via cp.async at kernel start; consumed by
//    epilogue group (mt=0,hf=0), overlapping 25% of the short DRAM read.
// ---------------------------------------------------------------------------
#define SC_SQHI 0
#define SC_SQLO 4608
#define SC_ASCS 9216
#define SC_REDM 13312
#define SC_REDS 15488
#define SC_REDM2 17664
#define SC_REDS2 17792
#define SC_SHORT 17920                 // 8 rows x 4112B = 32896
#define SC_SKHI 50816                  // 1024 x 64B = 65536 (128B aligned)
#define SC_SKLO 116352                 // 65536
#define SC_MASK 181888                 // 32 x 1040 = 33280
#define SC_TOTAL 215168

__global__ void __launch_bounds__(512, 1) scores_kernel(
    const float* __restrict__ shortp, float* __restrict__ out)
{
    extern __shared__ char smem_raw[];
    const int b = blockIdx.z;
    const int h = blockIdx.y;
    const int m0 = blockIdx.x * 32;
    const int bh = b * H + h;
    const int tid = threadIdx.x;
    const int lane = tid & 31;
    const int wid = tid >> 5;
    const unsigned sbase = sm_u32(smem_raw);

    // ---- stage mask bytes (32 rows x 1024) via cp.async ----
#pragma unroll
    for (int l = 0; l < 4; l++) {
        int f = tid + l * 512;
        int row = f >> 6, g = f & 63;
        cpa16(sbase + SC_MASK + row * 1040 + g * 16,
              g_mask8 + ((size_t)(b * S) + m0 + row) * S + g * 16);
    }
    // ---- stage short rows m0..m0+7 (8 x 4KB) via cp.async ----
#pragma unroll
    for (int l = 0; l < 4; l++) {
        int f = tid + l * 512;                 // 0..2047
        int row = f >> 8, g = f & 255;         // 8 rows x 256 granules
        cpa16(sbase + SC_SHORT + row * 4112 + g * 16,
              shortp + ((size_t)bh * S + m0 + row) * S + g * 4);
    }
    CP_COMMIT();

    {
        int row = tid >> 4, g = tid & 15;
        size_t goff = ((size_t)(b * S) + m0 + row) * D + h * DK + g * 4;
        *(uint2*)(smem_raw + SC_SQHI + row * 144 + g * 8) = *(const uint2*)(g_q_hi + goff);
        *(uint2*)(smem_raw + SC_SQLO + row * 144 + g * 8) = *(const uint2*)(g_q_lo + goff);
    }
    ((float2*)(smem_raw + SC_ASCS))[tid] = *(const float2*)(g_asco + (size_t)bh * S + tid * 2);

    float acc[2][8][4];
#pragma unroll
    for (int mt = 0; mt < 2; mt++)
#pragma unroll
        for (int nt = 0; nt < 8; nt++)
#pragma unroll
            for (int i = 0; i < 4; i++) acc[mt][nt][i] = 0.f;

    for (int chunk = 0; chunk < 2; chunk++) {
        if (chunk) __syncthreads();
        // K chunk (1024 rows x 32dk hi+lo): XOR-swizzled 64B-stride layout
#pragma unroll
        for (int l = 0; l < 8; l++) {
            int f = tid + l * 512;
            int row = f >> 2, g = f & 3;
            unsigned dsto = (unsigned)(row * 64 + ((g ^ ((row >> 1) & 3)) * 16));
            size_t goff = ((size_t)(b * S) + row) * D + h * DK + chunk * 32 + g * 8;
            *(uint4*)(smem_raw + SC_SKHI + dsto) = *(const uint4*)(g_k_hi + goff);
            *(uint4*)(smem_raw + SC_SKLO + dsto) = *(const uint4*)(g_k_lo + goff);
        }
        __syncthreads();

#pragma unroll
        for (int kk2 = 0; kk2 < 2; kk2++) {
            const int kglob = chunk * 2 + kk2;
            unsigned ahi[2][4], alo[2][4];
#pragma unroll
            for (int mt = 0; mt < 2; mt++) {
                unsigned rbytes = (unsigned)(mt * 16 + (lane & 7) + ((lane >> 3) & 1) * 8) * 144
                                + ((lane >> 4) & 1) * 16 + kglob * 32;
                ldsm4(ahi[mt], sbase + SC_SQHI + rbytes);
                ldsm4(alo[mt], sbase + SC_SQLO + rbytes);
            }
#pragma unroll
            for (int nt2 = 0; nt2 < 4; nt2++) {
                unsigned row = (unsigned)(wid * 64 + nt2 * 16 + (lane & 7) + ((lane >> 4) & 1) * 8);
                unsigned gread = (unsigned)(kk2 * 2 + ((lane >> 3) & 1));
                unsigned rbytes = row * 64 + ((gread ^ ((row >> 1) & 3)) * 16);
                unsigned bhi[4], blo[4];
                ldsm4(bhi, sbase + SC_SKHI + rbytes);
                ldsm4(blo, sbase + SC_SKLO + rbytes);
#pragma unroll
                for (int mt = 0; mt < 2; mt++) {
                    mma16816(acc[mt][nt2 * 2],     ahi[mt], bhi);
                    mma16816(acc[mt][nt2 * 2 + 1], ahi[mt], bhi + 2);
                    mma16816(acc[mt][nt2 * 2],     ahi[mt], blo);
                    mma16816(acc[mt][nt2 * 2 + 1], ahi[mt], blo + 2);
                    mma16816(acc[mt][nt2 * 2],     alo[mt], bhi);
                    mma16816(acc[mt][nt2 * 2 + 1], alo[mt], bhi + 2);
                }
            }
        }
    }

    CP_WAIT(0);       // mask + staged short complete
    __syncthreads();

    // ---- fused epilogue: /8 + asco + short, mask (smem bytes), softmax ----
    const int q = lane >> 2, tig = lane & 3;
    const float* ascf = (const float*)(smem_raw + SC_ASCS);
    float* redM = (float*)(smem_raw + SC_REDM);
    float* redS = (float*)(smem_raw + SC_REDS);
    float* redM2 = (float*)(smem_raw + SC_REDM2);
    float* redS2 = (float*)(smem_raw + SC_REDS2);

#pragma unroll
    for (int mt = 0; mt < 2; mt++) {
#pragma unroll
        for (int hf = 0; hf < 2; hf++) {
            int rl = mt * 16 + hf * 8 + q;
            int grow = m0 + rl;
            // rows 0..7 (mt==0 && hf==0) come from the cp.async-staged smem copy
            const float* shp = (mt == 0 && hf == 0)
                ? (const float*)(smem_raw + SC_SHORT + rl * 4112 + (wid * 64 + tig * 2) * 4)
                : shortp + ((size_t)bh * S + grow) * S + wid * 64 + tig * 2;
            const unsigned char* mrow =
                (const unsigned char*)(smem_raw + SC_MASK + rl * 1040 + wid * 64 + tig * 2);
            float mx = -1e30f;
#pragma unroll
            for (int nt = 0; nt < 8; nt++) {
                float2 sh = *(const float2*)(shp + nt * 8);
                uchar2 mk = *(const uchar2*)(mrow + nt * 8);
                int ci = wid * 64 + nt * 8 + tig * 2;
                float s0 = acc[mt][nt][hf * 2]     * 0.125f + ascf[ci]     + sh.x;
                float s1 = acc[mt][nt][hf * 2 + 1] * 0.125f + ascf[ci + 1] + sh.y;
                s0 = mk.x ? s0 : -1e9f;
                s1 = mk.y ? s1 : -1e9f;
                acc[mt][nt][hf * 2] = s0;
                acc[mt][nt][hf * 2 + 1] = s1;
                mx = fmaxf(mx, fmaxf(s0, s1));
            }
            mx = fmaxf(mx, __shfl_xor_sync(0xffffffffu, mx, 1));
            mx = fmaxf(mx, __shfl_xor_sync(0xffffffffu, mx, 2));
            if (tig == 0) redM[rl * 17 + wid] = mx;
        }
    }
    __syncthreads();
    if (tid < 32) {
        float m = redM[tid * 17];
#pragma unroll
        for (int w = 1; w < 16; w++) m = fmaxf(m, redM[tid * 17 + w]);
        redM2[tid] = m;
    }
    __syncthreads();

#pragma unroll
    for (int mt = 0; mt < 2; mt++) {
#pragma unroll
        for (int hf = 0; hf < 2; hf++) {
            int rl = mt * 16 + hf * 8 + q;
            float m = redM2[rl];
            float sum = 0.f;
#pragma unroll
            for (int nt = 0; nt < 8; nt++) {
                float e0 = __expf(acc[mt][nt][hf * 2] - m);
                float e1 = __expf(acc[mt][nt][hf * 2 + 1] - m);
                acc[mt][nt][hf * 2] = e0;
                acc[mt][nt][hf * 2 + 1] = e1;
                sum += e0 + e1;
            }
            sum += __shfl_xor_sync(0xffffffffu, sum, 1);
            sum += __shfl_xor_sync(0xffffffffu, sum, 2);
            if (tig == 0) redS[rl * 17 + wid] = sum;
        }
    }
    __syncthreads();
    if (tid < 32) {
        float s = 0.f;
#pragma unroll
        for (int w = 0; w < 16; w++) s += redS[tid * 17 + w];
        redS2[tid] = s;
    }
    __syncthreads();

#pragma unroll
    for (int mt = 0; mt < 2; mt++) {
#pragma unroll
        for (int hf = 0; hf < 2; hf++) {
            int rl = mt * 16 + hf * 8 + q;
            int grow = m0 + rl;
            float inv = 1.0f / redS2[rl];
            float* op = out + ((size_t)bh * S + grow) * S + wid * 64 + tig * 2;
#pragma unroll
            for (int nt = 0; nt < 8; nt++) {
                float2 o;
                o.x = acc[mt][nt][hf * 2] * inv;
                o.y = acc[mt][nt][hf * 2 + 1] * inv;
                *(float2*)(op + nt * 8) = o;
            }
        }
    }
}

// ---------------------------------------------------------------------------
extern "C" void kernel_launch(void* const* d_in, const int* in_sizes, int n_in,
                              void* d_out, int out_size)
{
    const float* query  = (const float*)d_in[0];
    const float* key    = (const float*)d_in[1];
    const int*   mask   = (const int*)  d_in[2];
    const float* aspect = (const float*)d_in[3];
    const float* shortp = (const float*)d_in[4];
    const float* Wq     = (const float*)d_in[5];
    const float* bq     = (const float*)d_in[6];
    const float* Wk     = (const float*)d_in[7];
    const float* bk     = (const float*)d_in[8];
    const float* Wd     = (const float*)d_in[9];
    const float* bd     = (const float*)d_in[10];
    const float* wm     = (const float*)d_in[11];
    const float* bm     = (const float*)d_in[12];
    float* out = (float*)d_out;

    cudaFuncSetAttribute(proj_kernel, cudaFuncAttributeMaxDynamicSharedMemorySize, 2 * PJ_BUF);
    cudaFuncSetAttribute(scores_kernel, cudaFuncAttributeMaxDynamicSharedMemorySize, SC_TOTAL);

    unsigned char* mask8;
    cudaGetSymbolAddress((void**)&mask8, g_mask8);

    const int nM4 = BATCH * S * S / 4;
    mask8_kernel<<<nM4 / 256, 256>>>(mask, mask8, nM4);

    aspect1_kernel<<<BATCH * H, 256>>>(aspect, Wd, bd, wm);

    dim3 gp(32, 8, 2);                      // M tiles, N tiles, {Q,K}
    proj_kernel<<<gp, 256, 2 * PJ_BUF>>>(query, Wq, bq, key, Wk, bk);

    dim3 ga(S / 16, BATCH * H);
    aspect2_kernel<<<ga, 128>>>(bm);

    dim3 gs(S / 32, H, BATCH);
    scores_kernel<<<gs, 512, SC_TOTAL>>>(shortp, out);
}

// round 14
// speedup vs baseline: 1.0727x; 1.0032x over previous
#include <cuda_runtime.h>
#include <cuda_bf16.h>

#define BATCH 4
#define S 1024
#define D 1024
#define H 16
#define DK 64

// ---------------------------------------------------------------------------
// scratch (allocation-free: __device__ globals), split bf16: v ~= hi + lo
// ---------------------------------------------------------------------------
__device__ __nv_bfloat16 g_q_hi[BATCH * S * D];
__device__ __nv_bfloat16 g_q_lo[BATCH * S * D];
__device__ __nv_bfloat16 g_k_hi[BATCH * S * D];
__device__ __nv_bfloat16 g_k_lo[BATCH * S * D];
__device__ float g_asco[BATCH * H * S];
__device__ float g_aw[BATCH * H * DK];             // aspect @ Wd @ weight_m
__device__ unsigned char g_mask8[BATCH * S * S];   // packed mask bytes

// ---------------------------------------------------------------------------
// helpers
// ---------------------------------------------------------------------------
__device__ __forceinline__ unsigned sm_u32(const void* p) {
    return (unsigned)__cvta_generic_to_shared(p);
}

__device__ __forceinline__ void ldsm4(unsigned r[4], unsigned addr) {
    asm volatile("ldmatrix.sync.aligned.m8n8.x4.shared.b16 {%0,%1,%2,%3}, [%4];"
                 : "=r"(r[0]), "=r"(r[1]), "=r"(r[2]), "=r"(r[3])
                 : "r"(addr));
}

__device__ __forceinline__ void mma16816(float* c, const unsigned* a, const unsigned* b) {
    asm volatile(
        "mma.sync.aligned.m16n8k16.row.col.f32.bf16.bf16.f32 "
        "{%0,%1,%2,%3}, {%4,%5,%6,%7}, {%8,%9}, {%0,%1,%2,%3};"
        : "+f"(c[0]), "+f"(c[1]), "+f"(c[2]), "+f"(c[3])
        : "r"(a[0]), "r"(a[1]), "r"(a[2]), "r"(a[3]), "r"(b[0]), "r"(b[1]));
}

__device__ __forceinline__ void split_pack(float x, float y, unsigned& hi, unsigned& lo) {
    __nv_bfloat162 h, l;
    h.x = __float2bfloat16(x);
    h.y = __float2bfloat16(y);
    l.x = __float2bfloat16(x - __bfloat162float(h.x));
    l.y = __float2bfloat16(y - __bfloat162float(h.y));
    hi = *reinterpret_cast<unsigned*>(&h);
    lo = *reinterpret_cast<unsigned*>(&l);
}

__device__ __forceinline__ void cpa16(unsigned dst, const void* src) {
    asm volatile("cp.async.cg.shared.global [%0], [%1], 16;" :: "r"(dst), "l"(src));
}
#define CP_COMMIT() asm volatile("cp.async.commit_group;")
#define CP_WAIT(N)  asm volatile("cp.async.wait_group %0;" :: "n"(N))

// ---------------------------------------------------------------------------
// Kernel 0: pack mask int32 {0,1} -> uint8 (exact).
// ---------------------------------------------------------------------------
__global__ __launch_bounds__(256) void mask8_kernel(
    const int* __restrict__ m, unsigned char* __restrict__ o, int n4)
{
    int i = blockIdx.x * 256 + threadIdx.x;
    if (i < n4) {
        int4 v = ((const int4*)m)[i];
        uchar4 u;
        u.x = (unsigned char)v.x; u.y = (unsigned char)v.y;
        u.z = (unsigned char)v.z; u.w = (unsigned char)v.w;
        ((uchar4*)o)[i] = u;
    }
}

// ---------------------------------------------------------------------------
// Kernel 1 (round-3 proven, 183us = mma.sync ceiling): C = X @ W^T + bias.
// ---------------------------------------------------------------------------
#define PJ_AHI 0
#define PJ_ALO 10240
#define PJ_BHI 20480
#define PJ_BLO 30720
#define PJ_BUF 40960

__global__ void __launch_bounds__(256, 1) proj_kernel(
    const float* __restrict__ Xq, const float* __restrict__ Wq, const float* __restrict__ bq,
    const float* __restrict__ Xk, const float* __restrict__ Wk, const float* __restrict__ bk)
{
    extern __shared__ char smem_raw[];
    const bool is_k = blockIdx.z != 0;
    const float* __restrict__ X = is_k ? Xk : Xq;
    const float* __restrict__ W = is_k ? Wk : Wq;
    const float* __restrict__ bias = is_k ? bk : bq;
    __nv_bfloat16* __restrict__ Chi = is_k ? g_k_hi : g_q_hi;
    __nv_bfloat16* __restrict__ Clo = is_k ? g_k_lo : g_q_lo;

    const int tid = threadIdx.x;
    const int lane = tid & 31;
    const int wid = tid >> 5;
    const int wm = wid & 3;
    const int wn = wid >> 2;
    const int m0 = blockIdx.x * 128;
    const int n0 = blockIdx.y * 128;
    const unsigned sbase = sm_u32(smem_raw);

    float acc[2][8][4];
#pragma unroll
    for (int mt = 0; mt < 2; mt++)
#pragma unroll
        for (int nt = 0; nt < 8; nt++)
#pragma unroll
            for (int i = 0; i < 4; i++) acc[mt][nt][i] = 0.f;

    float4 ra[4], rb[4];

#pragma unroll
    for (int l = 0; l < 4; l++) {
        int f = tid + l * 256;
        int row = f >> 3, c4 = f & 7;
        ra[l] = *(const float4*)(X + (size_t)(m0 + row) * D + c4 * 4);
        rb[l] = *(const float4*)(W + (size_t)(n0 + row) * D + c4 * 4);
    }
#pragma unroll
    for (int l = 0; l < 4; l++) {
        int f = tid + l * 256;
        int row = f >> 3, c4 = f & 7;
        unsigned h0, l0, h1, l1;
        split_pack(ra[l].x, ra[l].y, h0, l0);
        split_pack(ra[l].z, ra[l].w, h1, l1);
        *(uint2*)(smem_raw + PJ_AHI + row * 80 + c4 * 8) = make_uint2(h0, h1);
        *(uint2*)(smem_raw + PJ_ALO + row * 80 + c4 * 8) = make_uint2(l0, l1);
        split_pack(rb[l].x, rb[l].y, h0, l0);
        split_pack(rb[l].z, rb[l].w, h1, l1);
        *(uint2*)(smem_raw + PJ_BHI + row * 80 + c4 * 8) = make_uint2(h0, h1);
        *(uint2*)(smem_raw + PJ_BLO + row * 80 + c4 * 8) = make_uint2(l0, l1);
    }
    __syncthreads();

    for (int c = 0; c < 32; c++) {
        if (c < 31) {
            int k0 = (c + 1) * 32;
#pragma unroll
            for (int l = 0; l < 4; l++) {
                int f = tid + l * 256;
                int row = f >> 3, c4 = f & 7;
                ra[l] = *(const float4*)(X + (size_t)(m0 + row) * D + k0 + c4 * 4);
                rb[l] = *(const float4*)(W + (size_t)(n0 + row) * D + k0 + c4 * 4);
            }
        }
        {
            const unsigned base = sbase + (c & 1) * PJ_BUF;
#pragma unroll
            for (int kk = 0; kk < 2; kk++) {
                unsigned ahi[2][4], alo[2][4];
#pragma unroll
                for (int mt = 0; mt < 2; mt++) {
                    unsigned rbytes = (unsigned)(wm * 32 + mt * 16 + (lane & 7) + ((lane >> 3) & 1) * 8) * 80
                                    + ((lane >> 4) & 1) * 16 + kk * 32;
                    ldsm4(ahi[mt], base + PJ_AHI + rbytes);
                    ldsm4(alo[mt], base + PJ_ALO + rbytes);
                }
#pragma unroll
                for (int nt2 = 0; nt2 < 4; nt2++) {
                    unsigned rbytes = (unsigned)(wn * 64 + nt2 * 16 + (lane & 7) + ((lane >> 4) & 1) * 8) * 80
                                    + ((lane >> 3) & 1) * 16 + kk * 32;
                    unsigned bhi[4], blo[4];
                    ldsm4(bhi, base + PJ_BHI + rbytes);
                    ldsm4(blo, base + PJ_BLO + rbytes);
#pragma unroll
                    for (int mt = 0; mt < 2; mt++) {
                        mma16816(acc[mt][nt2 * 2],     ahi[mt], bhi);
                        mma16816(acc[mt][nt2 * 2 + 1], ahi[mt], bhi + 2);
                        mma16816(acc[mt][nt2 * 2],     ahi[mt], blo);
                        mma16816(acc[mt][nt2 * 2 + 1], ahi[mt], blo + 2);
                        mma16816(acc[mt][nt2 * 2],     alo[mt], bhi);
                        mma16816(acc[mt][nt2 * 2 + 1], alo[mt], bhi + 2);
                    }
                }
            }
        }
        if (c < 31) {
            char* dst = smem_raw + ((c + 1) & 1) * PJ_BUF;
#pragma unroll
            for (int l = 0; l < 4; l++) {
                int f = tid + l * 256;
                int row = f >> 3, c4 = f & 7;
                unsigned h0, l0, h1, l1;
                split_pack(ra[l].x, ra[l].y, h0, l0);
                split_pack(ra[l].z, ra[l].w, h1, l1);
                *(uint2*)(dst + PJ_AHI + row * 80 + c4 * 8) = make_uint2(h0, h1);
                *(uint2*)(dst + PJ_ALO + row * 80 + c4 * 8) = make_uint2(l0, l1);
                split_pack(rb[l].x, rb[l].y, h0, l0);
                split_pack(rb[l].z, rb[l].w, h1, l1);
                *(uint2*)(dst + PJ_BHI + row * 80 + c4 * 8) = make_uint2(h0, h1);
                *(uint2*)(dst + PJ_BLO + row * 80 + c4 * 8) = make_uint2(l0, l1);
            }
            __syncthreads();
        }
    }

    const int q = lane >> 2, tig = lane & 3;
#pragma unroll
    for (int mt = 0; mt < 2; mt++) {
#pragma unroll
        for (int nt = 0; nt < 8; nt++) {
            int col = n0 + wn * 64 + nt * 8 + tig * 2;
            float2 bb = *(const float2*)(bias + col);
            int row = m0 + wm * 32 + mt * 16 + q;
            unsigned hi, lo;
            split_pack(acc[mt][nt][0] + bb.x, acc[mt][nt][1] + bb.y, hi, lo);
            *reinterpret_cast<unsigned*>(&Chi[(size_t)row * D + col]) = hi;
            *reinterpret_cast<unsigned*>(&Clo[(size_t)row * D + col]) = lo;
            split_pack(acc[mt][nt][2] + bb.x, acc[mt][nt][3] + bb.y, hi, lo);
            *reinterpret_cast<unsigned*>(&Chi[(size_t)(row + 8) * D + col]) = hi;
            *reinterpret_cast<unsigned*>(&Clo[(size_t)(row + 8) * D + col]) = lo;
        }
    }
}

// ---------------------------------------------------------------------------
// Kernel 2a: aspect stage 1.
// ---------------------------------------------------------------------------
__global__ __launch_bounds__(256) void aspect1_kernel(
    const float* __restrict__ aspect, const float* __restrict__ Wd, const float* __restrict__ bd,
    const float* __restrict__ wm)
{
    const int bh = blockIdx.x;
    const int b = bh >> 4;
    const int h = bh & 15;
    const int tid = threadIdx.x;

    __shared__ float asp_s[64];

    {
        int e = tid >> 2, p = tid & 3;
        const float* av = aspect + (size_t)b * D + p * 256;
        const float* wv = Wd + (size_t)e * D + p * 256;
        float sum = 0.f;
#pragma unroll 4
        for (int d = 0; d < 256; d += 4) {
            float4 a = *(const float4*)(av + d);
            float4 w = *(const float4*)(wv + d);
            sum += a.x * w.x + a.y * w.y + a.z * w.z + a.w * w.w;
        }
        sum += __shfl_xor_sync(0xffffffffu, sum, 1, 4);
        sum += __shfl_xor_sync(0xffffffffu, sum, 2, 4);
        if (p == 0) asp_s[e] = sum + bd[e];
    }
    __syncthreads();
    if (tid < 64) {
        float s = 0.f;
        const float* w = wm + (size_t)h * DK * DK + tid;
#pragma unroll 8
        for (int c = 0; c < 64; c++) s += asp_s[c] * w[c * 64];
        g_aw[bh * DK + tid] = s;
    }
}

// ---------------------------------------------------------------------------
// Kernel 2b: aspect stage 2 (coalesced, measured 8.4us).
// ---------------------------------------------------------------------------
__global__ __launch_bounds__(128) void aspect2_kernel(const float* __restrict__ bm)
{
    const int bh = blockIdx.y;
    const int b = bh >> 4;
    const int h = bh & 15;
    const int tid = threadIdx.x;
    const int r = tid >> 3;
    const int g = tid & 7;
    const int j = blockIdx.x * 16 + r;

    __shared__ float aw_s[64];
    if (tid < 64) aw_s[tid] = g_aw[bh * DK + tid];
    __syncthreads();

    const size_t rowoff = ((size_t)b * S + j) * D + h * DK;
    uint4 vh = *(const uint4*)(g_k_hi + rowoff + g * 8);
    uint4 vl = *(const uint4*)(g_k_lo + rowoff + g * 8);

    const __nv_bfloat162* ph = reinterpret_cast<const __nv_bfloat162*>(&vh);
    const __nv_bfloat162* pl = reinterpret_cast<const __nv_bfloat162*>(&vl);
    float s = 0.f;
#pragma unroll
    for (int i = 0; i < 4; i++) {
        float2 a = __bfloat1622float2(ph[i]);
        float2 c = __bfloat1622float2(pl[i]);
        s += aw_s[g * 8 + 2 * i] * (a.x + c.x) + aw_s[g * 8 + 2 * i + 1] * (a.y + c.y);
    }
    s += __shfl_xor_sync(0xffffffffu, s, 1, 8);
    s += __shfl_xor_sync(0xffffffffu, s, 2, 8);
    s += __shfl_xor_sync(0xffffffffu, s, 4, 8);

    if (g == 0) {
        float x = s + bm[0];
        float t = 1.f - 2.f / (__expf(2.f * x) + 1.f);
        g_asco[(size_t)bh * S + j] = t;
    }
}

// ---------------------------------------------------------------------------
// Kernel 3 v4: fused scores + softmax.
// vs v3: ALL 32 short rows staged in smem. Rows 0..7 at kernel start (land
// during mma); rows 8..31 cp.async'd into the dead K buffers post-mma,
// overlapped with epilogue group (0,0) compute.
// ---------------------------------------------------------------------------
#define SC_SQHI 0
#define SC_SQLO 4608
#define SC_ASCS 9216
#define SC_REDM 13312
#define SC_REDS 15488
#define SC_REDM2 17664
#define SC_REDS2 17792
#define SC_SHORT 17920                 // 8 rows x 4112B = 32896
#define SC_SKHI 50816                  // K hi (65536); post-mma: short rows 8..31
#define SC_SKLO 116352                 // K lo (65536)
#define SC_MASK 181888                 // 32 x 1040 = 33280
#define SC_TOTAL 215168

__global__ void __launch_bounds__(512, 1) scores_kernel(
    const float* __restrict__ shortp, float* __restrict__ out)
{
    extern __shared__ char smem_raw[];
    const int b = blockIdx.z;
    const int h = blockIdx.y;
    const int m0 = blockIdx.x * 32;
    const int bh = b * H + h;
    const int tid = threadIdx.x;
    const int lane = tid & 31;
    const int wid = tid >> 5;
    const unsigned sbase = sm_u32(smem_raw);

    // ---- stage mask bytes (32 rows) + short rows 0..7 via cp.async ----
#pragma unroll
    for (int l = 0; l < 4; l++) {
        int f = tid + l * 512;
        int row = f >> 6, g = f & 63;
        cpa16(sbase + SC_MASK + row * 1040 + g * 16,
              g_mask8 + ((size_t)(b * S) + m0 + row) * S + g * 16);
    }
#pragma unroll
    for (int l = 0; l < 4; l++) {
        int f = tid + l * 512;
        int row = f >> 8, g = f & 255;
        cpa16(sbase + SC_SHORT + row * 4112 + g * 16,
              shortp + ((size_t)bh * S + m0 + row) * S + g * 4);
    }
    CP_COMMIT();

    {
        int row = tid >> 4, g = tid & 15;
        size_t goff = ((size_t)(b * S) + m0 + row) * D + h * DK + g * 4;
        *(uint2*)(smem_raw + SC_SQHI + row * 144 + g * 8) = *(const uint2*)(g_q_hi + goff);
        *(uint2*)(smem_raw + SC_SQLO + row * 144 + g * 8) = *(const uint2*)(g_q_lo + goff);
    }
    ((float2*)(smem_raw + SC_ASCS))[tid] = *(const float2*)(g_asco + (size_t)bh * S + tid * 2);

    float acc[2][8][4];
#pragma unroll
    for (int mt = 0; mt < 2; mt++)
#pragma unroll
        for (int nt = 0; nt < 8; nt++)
#pragma unroll
            for (int i = 0; i < 4; i++) acc[mt][nt][i] = 0.f;

    for (int chunk = 0; chunk < 2; chunk++) {
        if (chunk) __syncthreads();
#pragma unroll
        for (int l = 0; l < 8; l++) {
            int f = tid + l * 512;
            int row = f >> 2, g = f & 3;
            unsigned dsto = (unsigned)(row * 64 + ((g ^ ((row >> 1) & 3)) * 16));
            size_t goff = ((size_t)(b * S) + row) * D + h * DK + chunk * 32 + g * 8;
            *(uint4*)(smem_raw + SC_SKHI + dsto) = *(const uint4*)(g_k_hi + goff);
            *(uint4*)(smem_raw + SC_SKLO + dsto) = *(const uint4*)(g_k_lo + goff);
        }
        __syncthreads();

#pragma unroll
        for (int kk2 = 0; kk2 < 2; kk2++) {
            const int kglob = chunk * 2 + kk2;
            unsigned ahi[2][4], alo[2][4];
#pragma unroll
            for (int mt = 0; mt < 2; mt++) {
                unsigned rbytes = (unsigned)(mt * 16 + (lane & 7) + ((lane >> 3) & 1) * 8) * 144
                                + ((lane >> 4) & 1) * 16 + kglob * 32;
                ldsm4(ahi[mt], sbase + SC_SQHI + rbytes);
                ldsm4(alo[mt], sbase + SC_SQLO + rbytes);
            }
#pragma unroll
            for (int nt2 = 0; nt2 < 4; nt2++) {
                unsigned row = (unsigned)(wid * 64 + nt2 * 16 + (lane & 7) + ((lane >> 4) & 1) * 8);
                unsigned gread = (unsigned)(kk2 * 2 + ((lane >> 3) & 1));
                unsigned rbytes = row * 64 + ((gread ^ ((row >> 1) & 3)) * 16);
                unsigned bhi[4], blo[4];
                ldsm4(bhi, sbase + SC_SKHI + rbytes);
                ldsm4(blo, sbase + SC_SKLO + rbytes);
#pragma unroll
                for (int mt = 0; mt < 2; mt++) {
                    mma16816(acc[mt][nt2 * 2],     ahi[mt], bhi);
                    mma16816(acc[mt][nt2 * 2 + 1], ahi[mt], bhi + 2);
                    mma16816(acc[mt][nt2 * 2],     ahi[mt], blo);
                    mma16816(acc[mt][nt2 * 2 + 1], ahi[mt], blo + 2);
                    mma16816(acc[mt][nt2 * 2],     alo[mt], bhi);
                    mma16816(acc[mt][nt2 * 2 + 1], alo[mt], bhi + 2);
                }
            }
        }
    }

    // all warps done reading K smem; group A (mask + short 0..7) long landed
    CP_WAIT(0);
    __syncthreads();

    // ---- issue cp.async for short rows 8..31 into the dead K buffers ----
#pragma unroll
    for (int l = 0; l < 12; l++) {
        int f = tid + l * 512;                 // 0..6143
        int row = f >> 8, g = f & 255;         // 24 rows x 256 granules
        cpa16(sbase + SC_SKHI + row * 4112 + g * 16,
              shortp + ((size_t)bh * S + m0 + 8 + row) * S + g * 4);
    }
    CP_COMMIT();

    const int q = lane >> 2, tig = lane & 3;
    const float* ascf = (const float*)(smem_raw + SC_ASCS);
    float* redM = (float*)(smem_raw + SC_REDM);
    float* redS = (float*)(smem_raw + SC_REDS);
    float* redM2 = (float*)(smem_raw + SC_REDM2);
    float* redS2 = (float*)(smem_raw + SC_REDS2);

    // ---- epilogue group macro: score+mask+rowmax for rows rl(mt,hf) ----
#define EPI_GROUP(MT, HF, SHPTR_EXPR)                                          \
    {                                                                          \
        int rl = (MT) * 16 + (HF) * 8 + q;                                     \
        const float* shp = (SHPTR_EXPR);                                       \
        const unsigned char* mrow =                                            \
            (const unsigned char*)(smem_raw + SC_MASK + rl * 1040 + wid * 64 + tig * 2); \
        float mx = -1e30f;                                                     \
        _Pragma("unroll")                                                      \
        for (int nt = 0; nt < 8; nt++) {                                       \
            float2 sh = *(const float2*)(shp + nt * 8);                        \
            uchar2 mk = *(const uchar2*)(mrow + nt * 8);                       \
            int ci = wid * 64 + nt * 8 + tig * 2;                              \
            float s0 = acc[MT][nt][(HF) * 2]     * 0.125f + ascf[ci]     + sh.x; \
            float s1 = acc[MT][nt][(HF) * 2 + 1] * 0.125f + ascf[ci + 1] + sh.y; \
            s0 = mk.x ? s0 : -1e9f;                                            \
            s1 = mk.y ? s1 : -1e9f;                                            \
            acc[MT][nt][(HF) * 2] = s0;                                        \
            acc[MT][nt][(HF) * 2 + 1] = s1;                                    \
            mx = fmaxf(mx, fmaxf(s0, s1));                                     \
        }                                                                      \
        mx = fmaxf(mx, __shfl_xor_sync(0xffffffffu, mx, 1));                   \
        mx = fmaxf(mx, __shfl_xor_sync(0xffffffffu, mx, 2));                   \
        if (tig == 0) redM[rl * 17 + wid] = mx;                                \
    }

    // group (0,0): rows 0..7 from SC_SHORT (staged at kernel start)
    EPI_GROUP(0, 0,
        (const float*)(smem_raw + SC_SHORT + (q) * 4112 + (wid * 64 + tig * 2) * 4));

    // rows 8..31 staged copies must be complete and CTA-visible
    CP_WAIT(0);
    __syncthreads();

    // groups (0,1),(1,0),(1,1): rows 8..31 from SC_SKHI staging area
    EPI_GROUP(0, 1,
        (const float*)(smem_raw + SC_SKHI + (q) * 4112 + (wid * 64 + tig * 2) * 4));
    EPI_GROUP(1, 0,
        (const float*)(smem_raw + SC_SKHI + (8 + q) * 4112 + (wid * 64 + tig * 2) * 4));
    EPI_GROUP(1, 1,
        (const float*)(smem_raw + SC_SKHI + (16 + q) * 4112 + (wid * 64 + tig * 2) * 4));
#undef EPI_GROUP

    __syncthreads();
    if (tid < 32) {
        float m = redM[tid * 17];
#pragma unroll
        for (int w = 1; w < 16; w++) m = fmaxf(m, redM[tid * 17 + w]);
        redM2[tid] = m;
    }
    __syncthreads();

#pragma unroll
    for (int mt = 0; mt < 2; mt++) {
#pragma unroll
        for (int hf = 0; hf < 2; hf++) {
            int rl = mt * 16 + hf * 8 + q;
            float m = redM2[rl];
            float sum = 0.f;
#pragma unroll
            for (int nt = 0; nt < 8; nt++) {
                float e0 = __expf(acc[mt][nt][hf * 2] - m);
                float e1 = __expf(acc[mt][nt][hf * 2 + 1] - m);
                acc[mt][nt][hf * 2] = e0;
                acc[mt][nt][hf * 2 + 1] = e1;
                sum += e0 + e1;
            }
            sum += __shfl_xor_sync(0xffffffffu, sum, 1);
            sum += __shfl_xor_sync(0xffffffffu, sum, 2);
            if (tig == 0) redS[rl * 17 + wid] = sum;
        }
    }
    __syncthreads();
    if (tid < 32) {
        float s = 0.f;
#pragma unroll
        for (int w = 0; w < 16; w++) s += redS[tid * 17 + w];
        redS2[tid] = s;
    }
    __syncthreads();

#pragma unroll
    for (int mt = 0; mt < 2; mt++) {
#pragma unroll
        for (int hf = 0; hf < 2; hf++) {
            int rl = mt * 16 + hf * 8 + q;
            int grow = m0 + rl;
            float inv = 1.0f / redS2[rl];
            float* op = out + ((size_t)bh * S + grow) * S + wid * 64 + tig * 2;
#pragma unroll
            for (int nt = 0; nt < 8; nt++) {
                float2 o;
                o.x = acc[mt][nt][hf * 2] * inv;
                o.y = acc[mt][nt][hf * 2 + 1] * inv;
                *(float2*)(op + nt * 8) = o;
            }
        }
    }
}

// ---------------------------------------------------------------------------
extern "C" void kernel_launch(void* const* d_in, const int* in_sizes, int n_in,
                              void* d_out, int out_size)
{
    const float* query  = (const float*)d_in[0];
    const float* key    = (const float*)d_in[1];
    const int*   mask   = (const int*)  d_in[2];
    const float* aspect = (const float*)d_in[3];
    const float* shortp = (const float*)d_in[4];
    const float* Wq     = (const float*)d_in[5];
    const float* bq     = (const float*)d_in[6];
    const float* Wk     = (const float*)d_in[7];
    const float* bk     = (const float*)d_in[8];
    const float* Wd     = (const float*)d_in[9];
    const float* bd     = (const float*)d_in[10];
    const float* wm     = (const float*)d_in[11];
    const float* bm     = (const float*)d_in[12];
    float* out = (float*)d_out;

    cudaFuncSetAttribute(proj_kernel, cudaFuncAttributeMaxDynamicSharedMemorySize, 2 * PJ_BUF);
    cudaFuncSetAttribute(scores_kernel, cudaFuncAttributeMaxDynamicSharedMemorySize, SC_TOTAL);

    unsigned char* mask8;
    cudaGetSymbolAddress((void**)&mask8, g_mask8);

    const int nM4 = BATCH * S * S / 4;
    mask8_kernel<<<nM4 / 256, 256>>>(mask, mask8, nM4);

    aspect1_kernel<<<BATCH * H, 256>>>(aspect, Wd, bd, wm);

    dim3 gp(32, 8, 2);                      // M tiles, N tiles, {Q,K}
    proj_kernel<<<gp, 256, 2 * PJ_BUF>>>(query, Wq, bq, key, Wk, bk);

    dim3 ga(S / 16, BATCH * H);
    aspect2_kernel<<<ga, 128>>>(bm);

    dim3 gs(S / 32, H, BATCH);
    scores_kernel<<<gs, 512, SC_TOTAL>>>(shortp, out);
}